// round 14
// baseline (speedup 1.0000x reference)
#include <cuda_runtime.h>
#include <cstdint>
#include <math.h>

// ---------------- constants ----------------
#define S_    8192
#define DIM_  2048
#define H_    32
#define DH_   64
#define CBS_  64
#define NC_   128          // S/CBS
#define RS_   6272         // fused GEMM width: 6144 qkv + 96 comb + 32 pad (49*128)
#define KOFF_ 2048
#define VOFF_ 4096
#define CWOFF_ 6144
#define SCALE_ 0.125f
#define KSPLIT_ 4
#define NEGINF_ (-3.402823466e38f)
#define RMS_EPS_ 1.1920929e-07f

// ---------------- scratch ----------------
__device__ float g_x[S_ * DIM_];                      // rms-normed input (A-perm, tf32)
__device__ float g_wb1[RS_ * DIM_];                   // [wqkv|wcomb|0]^T (B-perm, tf32)
__device__ float g_wb2[DIM_ * DIM_];                  // w_out^T          (B-perm, tf32)
__device__ float g_y[S_ * DIM_];                      // combined branches (A-perm, tf32)
__device__ float g_qkv[S_ * RS_];                     // q|k|v|comb-logits (row-major)
__device__ float g_ap[64 * 128 * 4096];               // conv A (A-perm tf32)
__device__ float g_wtp[64 * 64 * 4096];               // conv W (B-perm tf32)
__device__ float g_part[2][KSPLIT_][H_ * NC_ * DH_];  // conv split-K partials
__device__ float g_ckv[2][H_ * NC_ * DH_];             // compressed k / v

// ================= PTX helpers =================
__device__ __forceinline__ uint32_t smem_u32(const void* p) {
    uint32_t a;
    asm("{ .reg .u64 t; cvta.to.shared.u64 t, %1; cvt.u32.u64 %0, t; }" : "=r"(a) : "l"(p));
    return a;
}
#define CP_ASYNC16(so, g) asm volatile("cp.async.cg.shared.global [%0], [%1], 16;" :: "r"(so), "l"(g) : "memory")
#define CP_COMMIT()  asm volatile("cp.async.commit_group;" ::: "memory")
#define CP_WAIT0()   asm volatile("cp.async.wait_group 0;" ::: "memory")
#define CP_WAIT1()   asm volatile("cp.async.wait_group 1;" ::: "memory")

__device__ __forceinline__ float to_tf32f(float x) {
    uint32_t u;
    asm("cvt.rna.tf32.f32 %0, %1;" : "=r"(u) : "f"(x));
    return __uint_as_float(u);
}
__device__ __forceinline__ void mma_tf32(float* c, const uint32_t* a, const uint32_t* b) {
    asm volatile("mma.sync.aligned.m16n8k8.row.col.f32.tf32.tf32.f32 "
                 "{%0,%1,%2,%3},{%4,%5,%6,%7},{%8,%9},{%0,%1,%2,%3};"
                 : "+f"(c[0]), "+f"(c[1]), "+f"(c[2]), "+f"(c[3])
                 : "r"(a[0]), "r"(a[1]), "r"(a[2]), "r"(a[3]), "r"(b[0]), "r"(b[1]));
}

// permuted index helpers (float index)
__device__ __forceinline__ size_t apermi(int m, int k, int K) {
    int lane = ((m & 7) << 2) + (k & 3);
    int e = ((m >> 3) & 1) | (((k >> 2) & 1) << 1);
    return ((((size_t)(m >> 4)) * (K >> 3) + (k >> 3)) << 7) + (lane << 2) + e;
}
__device__ __forceinline__ size_t bpermi(int n, int k, int K) {
    int lane = ((n & 7) << 2) + (k & 3);
    int e = (k >> 2) & 3;
    return ((((size_t)(n >> 3)) * (K >> 4) + (k >> 4)) << 7) + (lane << 2) + e;
}
// P A-perm word within a 16-row warp tile (cols = kv)
__device__ __forceinline__ int pword(int m, int c) {
    return ((c >> 3) << 7) + (((m & 7) << 2) + (c & 3)) * 4 + ((m >> 3) & 1) + (((c >> 2) & 1) << 1);
}
__device__ __forceinline__ int vrot(int l) { return ((l & 3) << 3) | (l >> 2); }

// ====== tf32 tensor-core GEMM: CTA 128x128, 4 warps (64x64), 2 stages, 3 CTAs/SM ======
__global__ __launch_bounds__(128, 3) void k_tgemm(const float* __restrict__ A,
                                                  const float* __restrict__ B,
                                                  float* __restrict__ C, int N, int K) {
    extern __shared__ float sm[];
    const uint32_t sbase = smem_u32(sm);
    const int tid = threadIdx.x;
    const int wid = tid >> 5, lane = tid & 31;
    const int g = lane >> 2, t = lane & 3;
    const int bm = blockIdx.y * 128, bn = blockIdx.x * 128;
    const int mbw = (wid >> 1) * 4;
    const int nbw = (wid & 1) * 8;
    const int KB8 = K >> 3, KB16 = K >> 4;
    const int NK = K >> 5;

    float acc[4][8][4];
    #pragma unroll
    for (int i = 0; i < 4; i++)
        #pragma unroll
        for (int j = 0; j < 8; j++)
            #pragma unroll
            for (int e = 0; e < 4; e++) acc[i][j][e] = 0.f;

    auto load_stage = [&](int kt, int s) {
        #pragma unroll
        for (int it = 0; it < 16; it++) {
            int seg = tid + it * 128;
            int blk = (seg >> 5) & 31;
            int w16 = seg & 31;
            const float* gp;
            if (seg < 1024) {
                int mbl = blk >> 2, kbl = blk & 3;
                gp = A + ((((size_t)(bm >> 4) + mbl) * KB8 + (kt << 2) + kbl) << 7) + (w16 << 2);
            } else {
                int nbl = blk >> 1, kbl = blk & 1;
                gp = B + ((((size_t)(bn >> 3) + nbl) * KB16 + (kt << 1) + kbl) << 7) + (w16 << 2);
            }
            uint32_t so = sbase + s * 32768 + (seg << 4);
            CP_ASYNC16(so, gp);
        }
        CP_COMMIT();
    };

    load_stage(0, 0);

    for (int kt = 0; kt < NK; kt++) {
        CP_WAIT0();
        __syncthreads();
        if (kt + 1 < NK) load_stage(kt + 1, (kt + 1) & 1);
        const float* As = sm + (kt & 1) * 8192;
        const float* Bs = As + 4096;
        #pragma unroll
        for (int kp = 0; kp < 2; kp++) {
            uint32_t bfr[8][4];
            #pragma unroll
            for (int j = 0; j < 8; j++)
                *(uint4*)bfr[j] = *(const uint4*)(Bs + (((nbw + j) << 1) + kp) * 128 + (lane << 2));
            #pragma unroll
            for (int h2 = 0; h2 < 2; h2++) {
                int ks = kp * 2 + h2;
                uint32_t afr[4][4];
                #pragma unroll
                for (int i = 0; i < 4; i++)
                    *(uint4*)afr[i] = *(const uint4*)(As + (((mbw + i) << 2) + ks) * 128 + (lane << 2));
                #pragma unroll
                for (int i = 0; i < 4; i++)
                    #pragma unroll
                    for (int j = 0; j < 8; j++) mma_tf32(acc[i][j], afr[i], &bfr[j][2 * h2]);
            }
        }
    }

    #pragma unroll
    for (int i = 0; i < 4; i++)
        #pragma unroll
        for (int j = 0; j < 8; j++) {
            int row = bm + (mbw + i) * 16 + g;
            int col = bn + (nbw + j) * 8 + 2 * t;
            *(float2*)(C + (size_t)row * N + col) = make_float2(acc[i][j][0], acc[i][j][1]);
            *(float2*)(C + (size_t)(row + 8) * N + col) = make_float2(acc[i][j][2], acc[i][j][3]);
        }
}

// ================= conv as tensor-core GEMM, split-K=4 =====================
__global__ __launch_bounds__(256, 2) void k_tconv() {
    extern __shared__ float sm[];
    const uint32_t sbase = smem_u32(sm);
    const int tid = threadIdx.x;
    const int wid = tid >> 5, lane = tid & 31;
    const int g = lane >> 2, t = lane & 3;
    const int ksp = blockIdx.x;
    const int b = blockIdx.y;
    const float* A = g_ap + (size_t)b * 524288;
    const float* B = g_wtp + (size_t)b * 262144;
    const int mbw = (wid >> 1) * 2;
    const int nbw = (wid & 1) * 4;

    float acc[2][4][4];
    #pragma unroll
    for (int i = 0; i < 2; i++)
        #pragma unroll
        for (int j = 0; j < 4; j++)
            #pragma unroll
            for (int e = 0; e < 4; e++) acc[i][j][e] = 0.f;

    auto load_stage = [&](int kt, int s) {
        #pragma unroll
        for (int it = 0; it < 6; it++) {
            int seg = tid + it * 256;
            const float* gp;
            uint32_t so;
            if (seg < 1024) {
                int blk = seg >> 5, w16 = seg & 31;
                int mbl = blk >> 2, kbl = blk & 3;
                gp = A + (((size_t)mbl * 512 + (kt << 2) + kbl) << 7) + (w16 << 2);
                so = sbase + s * 24576 + (seg << 4);
            } else {
                int sb = seg - 1024;
                int blk = sb >> 5, w16 = sb & 31;
                int nbl = blk >> 1, kbl = blk & 1;
                gp = B + (((size_t)nbl * 256 + (kt << 1) + kbl) << 7) + (w16 << 2);
                so = sbase + s * 24576 + 16384 + (sb << 4);
            }
            CP_ASYNC16(so, gp);
        }
        CP_COMMIT();
    };

    const int kt0 = ksp * 32;
    load_stage(kt0, 0);
    load_stage(kt0 + 1, 1);

    for (int kk = 0; kk < 32; kk++) {
        int s = kk - (kk / 3) * 3;
        CP_WAIT1();
        __syncthreads();
        if (kk + 2 < 32) {
            int s2 = (kk + 2) - ((kk + 2) / 3) * 3;
            load_stage(kt0 + kk + 2, s2);
        } else CP_COMMIT();
        const float* As = sm + s * 6144;
        const float* Bs = As + 4096;
        #pragma unroll
        for (int kp = 0; kp < 2; kp++) {
            uint32_t bfr[4][4];
            #pragma unroll
            for (int j = 0; j < 4; j++)
                *(uint4*)bfr[j] = *(const uint4*)(Bs + (((nbw + j) << 1) + kp) * 128 + (lane << 2));
            #pragma unroll
            for (int h2 = 0; h2 < 2; h2++) {
                int ks4 = kp * 2 + h2;
                uint32_t afr[2][4];
                #pragma unroll
                for (int i = 0; i < 2; i++)
                    *(uint4*)afr[i] = *(const uint4*)(As + (((mbw + i) << 2) + ks4) * 128 + (lane << 2));
                #pragma unroll
                for (int i = 0; i < 2; i++)
                    #pragma unroll
                    for (int j = 0; j < 4; j++) mma_tf32(acc[i][j], afr[i], &bfr[j][2 * h2]);
            }
        }
    }

    int kv = b >> 5, h = b & 31;
    float* out = g_part[kv][ksp] + h * 8192;
    #pragma unroll
    for (int i = 0; i < 2; i++)
        #pragma unroll
        for (int j = 0; j < 4; j++) {
            int row = (mbw + i) * 16 + g;
            int col = (nbw + j) * 8 + 2 * t;
            *(float2*)(out + row * 64 + col) = make_float2(acc[i][j][0], acc[i][j][1]);
            *(float2*)(out + (row + 8) * 64 + col) = make_float2(acc[i][j][2], acc[i][j][3]);
        }
}

// ---------------- conv A build (vectorized) ----------------
__global__ void k_addpos(const float* __restrict__ kpos, const float* __restrict__ vpos) {
    int n = blockIdx.x;
    int b = blockIdx.y;
    int kv = b >> 5, h = b & 31;
    const float* pos = (kv ? vpos : kpos) + h * 4096;
    const int coloff = (kv ? VOFF_ : KOFF_) + h * 64;
    float* dst = g_ap + (size_t)b * 524288;
    const int lb = (n & 7) << 2;
    const int e0 = (n >> 3) & 1;
    for (int q = threadIdx.x; q < 1024; q += 256) {
        int c = q << 2;                      // kappa base, 4-aligned
        int t = c >> 6, i = c & 63;
        float4 a4 = *(const float4*)(g_qkv + (size_t)(n * 64 + t) * RS_ + coloff + i);
        float4 p4 = *(const float4*)(pos + c);
        float vals[4] = {a4.x + p4.x, a4.y + p4.y, a4.z + p4.z, a4.w + p4.w};
        int e = e0 | (((c >> 2) & 1) << 1);
        float* dstb = dst + ((((size_t)(n >> 4)) * 512 + (c >> 3)) << 7) + e;
        #pragma unroll
        for (int s = 0; s < 4; s++)
            dstb[(lb + s) << 2] = to_tf32f(vals[s]);
    }
}

// ---------------- conv weights -> B-perm tf32 ----------------
__global__ void k_prepw(const float* __restrict__ kcw, const float* __restrict__ vcw) {
    __shared__ float ts[64 * 65];
    int o = blockIdx.x;
    int b = blockIdx.y;
    int kv = b >> 5, h = b & 31;
    const float* src = (kv ? vcw : kcw) + (size_t)(h * 64 + o) * 4096;
    float* dst = g_wtp + (size_t)b * 262144;
    int tid = threadIdx.x;
    #pragma unroll
    for (int rep = 0; rep < 16; rep++) {
        int i = rep * 4 + (tid >> 6);
        int t = tid & 63;
        ts[t * 65 + i] = src[i * 64 + t];
    }
    __syncthreads();
    #pragma unroll
    for (int rep = 0; rep < 16; rep++) {
        int kappa = rep * 256 + tid;
        int t = kappa >> 6, i = kappa & 63;
        dst[bpermi(o, kappa, 4096)] = to_tf32f(ts[t * 65 + i]);
    }
}

// ---------------- rms norm -> A-perm tf32 ----------------
__global__ void k_rmsnorm(const float* __restrict__ inp, const float* __restrict__ w) {
    int row = blockIdx.x;
    const float* p = inp + (size_t)row * DIM_;
    float ss = 0.f;
    for (int c = threadIdx.x; c < DIM_; c += 256) { float v = p[c]; ss += v * v; }
    #pragma unroll
    for (int o = 16; o > 0; o >>= 1) ss += __shfl_xor_sync(0xffffffffu, ss, o);
    __shared__ float red[8];
    __shared__ float scs;
    if ((threadIdx.x & 31) == 0) red[threadIdx.x >> 5] = ss;
    __syncthreads();
    if (threadIdx.x == 0) {
        float tt = 0.f;
        #pragma unroll
        for (int v = 0; v < 8; v++) tt += red[v];
        scs = rsqrtf(tt * (1.f / (float)DIM_) + RMS_EPS_);
    }
    __syncthreads();
    float sc = scs;
    for (int c = threadIdx.x; c < DIM_; c += 256)
        g_x[apermi(row, c, DIM_)] = to_tf32f(p[c] * sc * w[c]);
}

// ---------------- transpose + concat -> B-perm tf32 ----------------
__global__ void k_prepbt(const float* __restrict__ s0, int c0,
                         const float* __restrict__ s1, int c1,
                         float* __restrict__ o) {
    __shared__ float t[32][33];
    int nt = blockIdx.x * 32, kt = blockIdx.y * 32;
    int tx = threadIdx.x, ty = threadIdx.y;
    #pragma unroll
    for (int r = ty; r < 32; r += 8) {
        int k = kt + r, n = nt + tx;
        float v = 0.f;
        if (n < c0) v = s0[(size_t)k * c0 + n];
        else if (s1 && n < c0 + c1) v = s1[(size_t)k * c1 + (n - c0)];
        t[r][tx] = v;
    }
    __syncthreads();
    #pragma unroll
    for (int r = ty; r < 32; r += 8) {
        int n = nt + r, k = kt + tx;
        o[bpermi(n, k, 2048)] = to_tf32f(t[tx][r]);
    }
}

// ---------------- conv split-K reduce + bias (vectorized) ----------------
__global__ void k_convred(const float* __restrict__ kcb, const float* __restrict__ vcb) {
    int idx = blockIdx.x * 256 + threadIdx.x;   // float4 index, 2*per/4 total
    const int per4 = (H_ * NC_ * DH_) >> 2;     // 65536
    if (idx >= 2 * per4) return;
    int kv = idx / per4;
    int rem = idx - kv * per4;
    float4 s = *(const float4*)(&g_part[kv][0][rem << 2]);
    #pragma unroll
    for (int ks = 1; ks < KSPLIT_; ks++) {
        float4 p = *(const float4*)(&g_part[kv][ks][rem << 2]);
        s.x += p.x; s.y += p.y; s.z += p.z; s.w += p.w;
    }
    int elem = rem << 2;
    int h = elem >> 13;
    int o = elem & 63;
    float4 bia = *(const float4*)((kv ? vcb : kcb) + h * 64 + o);
    s.x += bia.x; s.y += bia.y; s.z += bia.z; s.w += bia.w;
    *(float4*)(&g_ckv[kv][elem]) = s;
}

// ---- vectorized fills: K (LDG.128 + 4 rotated STS.32), V (4 LDG.32 + STS.128) ----
__device__ __forceinline__ void fill_k(float* Ksm, const float* rowbase, size_t rowstride,
                                       int tid) {
    #pragma unroll
    for (int it = 0; it < 8; it++) {
        int f = tid + it * 256;
        int kv = f >> 4, q = f & 15;
        float4 v4 = *(const float4*)(rowbase + (size_t)kv * rowstride + 4 * q);
        float vals[4] = {v4.x, v4.y, v4.z, v4.w};
        float* dstb = Ksm + ((((kv >> 3) << 2) + (q >> 2)) << 7) + (q & 3);
        int lb = (kv & 7) << 2;
        #pragma unroll
        for (int s = 0; s < 4; s++) {
            int c = (s + (q >> 2)) & 3;
            dstb[(lb + c) << 2] = to_tf32f(vals[c]);
        }
    }
}
__device__ __forceinline__ void fill_v(float* Vsm, const float* rowbase, size_t rowstride,
                                       int tid) {
    #pragma unroll
    for (int it = 0; it < 8; it++) {
        int f = tid + it * 256;
        int d = f & 63, rem = f >> 6;
        int kv16 = rem >> 2, kvlow = rem & 3;
        int kvb = (kv16 << 4) + kvlow;
        const float* s0 = rowbase + (size_t)kvb * rowstride + d;
        float4 o;
        o.x = to_tf32f(s0[0]);
        o.y = to_tf32f(s0[4 * rowstride]);
        o.z = to_tf32f(s0[8 * rowstride]);
        o.w = to_tf32f(s0[12 * rowstride]);
        int lane = (kvlow << 3) + (d & 7);
        *(float4*)(Vsm + ((((d >> 3) << 3) + kv16) << 7) + (lane << 2)) = o;
    }
}

// ===== merged attention: compressed (regs) + local (online) + fused combine =====
__global__ __launch_bounds__(256, 1) void k_attn(const float* __restrict__ bcomb) {
    extern __shared__ float smA[];
    float* Ksm = smA;
    float* Vsm = smA + 8192;
    float* Psm = smA + 16384;
    int a = blockIdx.x, h = blockIdx.y;
    int tid = threadIdx.x, w = tid >> 5, lane = tid & 31;
    int g = lane >> 2, t = lane & 3;
    int r0 = w * 16 + g, r1 = r0 + 8;
    int vr = vrot(lane);
    float* Pw = Psm + w * 2048;

    uint32_t qfr[8][4];
    {
        const float* qb = g_qkv + (size_t)(a * 128 + w * 16) * RS_ + h * 64;
        #pragma unroll
        for (int ks = 0; ks < 8; ks++) {
            qfr[ks][0] = __float_as_uint(to_tf32f(qb[(size_t)g * RS_ + ks * 8 + t]));
            qfr[ks][1] = __float_as_uint(to_tf32f(qb[(size_t)(g + 8) * RS_ + ks * 8 + t]));
            qfr[ks][2] = __float_as_uint(to_tf32f(qb[(size_t)g * RS_ + ks * 8 + t + 4]));
            qfr[ks][3] = __float_as_uint(to_tf32f(qb[(size_t)(g + 8) * RS_ + ks * 8 + t + 4]));
        }
    }

    // ---------------- phase C: compressed branch -> oc (normalized) --------------
    float oc[8][4];
    {
        const int qskip = a >> 4;
        const int kpskip = a >> 3;
        fill_k(Ksm, g_ckv[0] + h * 8192, 64, tid);
        fill_v(Vsm, g_ckv[1] + h * 8192, 64, tid);
        __syncthreads();

        float sacc[16][4];
        #pragma unroll
        for (int jb = 0; jb < 16; jb++)
            #pragma unroll
            for (int e = 0; e < 4; e++) sacc[jb][e] = 0.f;
        #pragma unroll
        for (int qq = 0; qq < 4; qq++) {
            if (qq < qskip) continue;
            #pragma unroll
            for (int kp = 0; kp < 4; kp++) {
                uint32_t bfr[4][4];
                #pragma unroll
                for (int j = 0; j < 4; j++)
                    *(uint4*)bfr[j] = *(const uint4*)(Ksm + ((((qq * 4 + j) << 2) + kp) << 7) + lane * 4);
                #pragma unroll
                for (int h2 = 0; h2 < 2; h2++) {
                    int ks = kp * 2 + h2;
                    #pragma unroll
                    for (int j = 0; j < 4; j++)
                        mma_tf32(sacc[qq * 4 + j], qfr[ks], &bfr[j][2 * h2]);
                }
            }
        }

        int th0 = (a * 128 + r0) >> 6;
        int th1 = (a * 128 + r1) >> 6;
        float mx0 = NEGINF_, mx1 = NEGINF_;
        #pragma unroll
        for (int qq = 0; qq < 4; qq++) {
            if (qq < qskip) continue;
            #pragma unroll
            for (int j = 0; j < 4; j++) {
                int jb = qq * 4 + j;
                int c0 = jb * 8 + 2 * t, c1 = c0 + 1;
                sacc[jb][0] = (c0 >= th0) ? sacc[jb][0] * SCALE_ : NEGINF_;
                sacc[jb][1] = (c1 >= th0) ? sacc[jb][1] * SCALE_ : NEGINF_;
                sacc[jb][2] = (c0 >= th1) ? sacc[jb][2] * SCALE_ : NEGINF_;
                sacc[jb][3] = (c1 >= th1) ? sacc[jb][3] * SCALE_ : NEGINF_;
                mx0 = fmaxf(mx0, fmaxf(sacc[jb][0], sacc[jb][1]));
                mx1 = fmaxf(mx1, fmaxf(sacc[jb][2], sacc[jb][3]));
            }
        }
        mx0 = fmaxf(mx0, __shfl_xor_sync(0xffffffffu, mx0, 1));
        mx0 = fmaxf(mx0, __shfl_xor_sync(0xffffffffu, mx0, 2));
        mx1 = fmaxf(mx1, __shfl_xor_sync(0xffffffffu, mx1, 1));
        mx1 = fmaxf(mx1, __shfl_xor_sync(0xffffffffu, mx1, 2));
        float s0 = 0.f, s1 = 0.f;
        #pragma unroll
        for (int qq = 0; qq < 4; qq++) {
            if (qq < qskip) continue;
            #pragma unroll
            for (int j = 0; j < 4; j++) {
                int jb = qq * 4 + j;
                sacc[jb][0] = __expf(sacc[jb][0] - mx0);
                sacc[jb][1] = __expf(sacc[jb][1] - mx0);
                sacc[jb][2] = __expf(sacc[jb][2] - mx1);
                sacc[jb][3] = __expf(sacc[jb][3] - mx1);
                s0 += sacc[jb][0] + sacc[jb][1];
                s1 += sacc[jb][2] + sacc[jb][3];
                int c0 = jb * 8 + 2 * t;
                Pw[pword(g, c0)]     = to_tf32f(sacc[jb][0]);
                Pw[pword(g, c0 + 1)] = to_tf32f(sacc[jb][1]);
                Pw[pword(g + 8, c0)]     = to_tf32f(sacc[jb][2]);
                Pw[pword(g + 8, c0 + 1)] = to_tf32f(sacc[jb][3]);
            }
        }
        s0 += __shfl_xor_sync(0xffffffffu, s0, 1);
        s0 += __shfl_xor_sync(0xffffffffu, s0, 2);
        s1 += __shfl_xor_sync(0xffffffffu, s1, 1);
        s1 += __shfl_xor_sync(0xffffffffu, s1, 2);
        __syncwarp();

        #pragma unroll
        for (int nb = 0; nb < 8; nb++)
            #pragma unroll
            for (int e = 0; e < 4; e++) oc[nb][e] = 0.f;
        #pragma unroll
        for (int kp = 0; kp < 8; kp++) {
            if (kp < kpskip) continue;
            uint32_t bfr[8][4];
            #pragma unroll
            for (int nb = 0; nb < 8; nb++)
                *(uint4*)bfr[nb] = *(const uint4*)(Vsm + (((nb << 3) + kp) << 7) + vr * 4);
            #pragma unroll
            for (int h2 = 0; h2 < 2; h2++) {
                int ks = kp * 2 + h2;
                uint32_t afr[4];
                *(uint4*)afr = *(const uint4*)(Pw + (ks << 7) + lane * 4);
                #pragma unroll
                for (int nb = 0; nb < 8; nb++)
                    mma_tf32(oc[nb], afr, &bfr[nb][2 * h2]);
            }
        }
        float inv0 = 1.f / s0, inv1 = 1.f / s1;
        #pragma unroll
        for (int nb = 0; nb < 8; nb++) {
            oc[nb][0] *= inv0; oc[nb][1] *= inv0;
            oc[nb][2] *= inv1; oc[nb][3] *= inv1;
        }
    }

    // ---------------- phase L: local branch (online over 2 tiles) ----------------
    float m0 = NEGINF_, m1 = NEGINF_, l0 = 0.f, l1 = 0.f;
    float oacc[8][4];
    #pragma unroll
    for (int nb = 0; nb < 8; nb++)
        #pragma unroll
        for (int e = 0; e < 4; e++) oacc[nb][e] = 0.f;
    int tstart = (a == 0) ? 1 : 0;

    for (int tile = tstart; tile < 2; tile++) {
        __syncthreads();
        int jbase = (a - 1 + tile) * 128;
        {
            const float* kb = g_qkv + (size_t)jbase * RS_ + KOFF_ + h * 64;
            const float* vb = g_qkv + (size_t)jbase * RS_ + VOFF_ + h * 64;
            fill_k(Ksm, kb, RS_, tid);
            fill_v(Vsm, vb, RS_, tid);
        }
        __syncthreads();

        int qlo = (tile == 0) ? (w >> 1) : 0;
        int qhi = (tile == 0) ? 4 : ((w >> 1) + 1);
        int kplo = (tile == 0) ? w : 0;
        int kphi = (tile == 0) ? 8 : (w + 1);

        float sacc[16][4];
        #pragma unroll
        for (int jb = 0; jb < 16; jb++)
            #pragma unroll
            for (int e = 0; e < 4; e++) sacc[jb][e] = 0.f;
        #pragma unroll
        for (int qq = 0; qq < 4; qq++) {
            if (qq < qlo || qq >= qhi) continue;
            #pragma unroll
            for (int kp = 0; kp < 4; kp++) {
                uint32_t bfr[4][4];
                #pragma unroll
                for (int j = 0; j < 4; j++)
                    *(uint4*)bfr[j] = *(const uint4*)(Ksm + ((((qq * 4 + j) << 2) + kp) << 7) + lane * 4);
                #pragma unroll
                for (int h2 = 0; h2 < 2; h2++) {
                    int ks = kp * 2 + h2;
                    #pragma unroll
                    for (int j = 0; j < 4; j++)
                        mma_tf32(sacc[qq * 4 + j], qfr[ks], &bfr[j][2 * h2]);
                }
            }
        }

        float rm0 = NEGINF_, rm1 = NEGINF_;
        #pragma unroll
        for (int qq = 0; qq < 4; qq++) {
            if (qq < qlo || qq >= qhi) continue;
            #pragma unroll
            for (int j = 0; j < 4; j++) {
                int jb = qq * 4 + j;
                int c0 = jb * 8 + 2 * t, c1 = c0 + 1;
                bool a00, a01, a10, a11;
                if (tile == 0) { a00 = c0 >= r0; a01 = c1 >= r0; a10 = c0 >= r1; a11 = c1 >= r1; }
                else           { a00 = c0 <= r0; a01 = c1 <= r0; a10 = c0 <= r1; a11 = c1 <= r1; }
                sacc[jb][0] = a00 ? sacc[jb][0] * SCALE_ : NEGINF_;
                sacc[jb][1] = a01 ? sacc[jb][1] * SCALE_ : NEGINF_;
                sacc[jb][2] = a10 ? sacc[jb][2] * SCALE_ : NEGINF_;
                sacc[jb][3] = a11 ? sacc[jb][3] * SCALE_ : NEGINF_;
                rm0 = fmaxf(rm0, fmaxf(sacc[jb][0], sacc[jb][1]));
                rm1 = fmaxf(rm1, fmaxf(sacc[jb][2], sacc[jb][3]));
            }
        }
        rm0 = fmaxf(rm0, __shfl_xor_sync(0xffffffffu, rm0, 1));
        rm0 = fmaxf(rm0, __shfl_xor_sync(0xffffffffu, rm0, 2));
        rm1 = fmaxf(rm1, __shfl_xor_sync(0xffffffffu, rm1, 1));
        rm1 = fmaxf(rm1, __shfl_xor_sync(0xffffffffu, rm1, 2));
        float mn0 = fmaxf(m0, rm0), mn1 = fmaxf(m1, rm1);
        float corr0 = __expf(m0 - mn0), corr1 = __expf(m1 - mn1);
        float rs0 = 0.f, rs1 = 0.f;
        #pragma unroll
        for (int qq = 0; qq < 4; qq++) {
            if (qq < qlo || qq >= qhi) continue;
            #pragma unroll
            for (int j = 0; j < 4; j++) {
                int jb = qq * 4 + j;
                sacc[jb][0] = __expf(sacc[jb][0] - mn0);
                sacc[jb][1] = __expf(sacc[jb][1] - mn0);
                sacc[jb][2] = __expf(sacc[jb][2] - mn1);
                sacc[jb][3] = __expf(sacc[jb][3] - mn1);
                rs0 += sacc[jb][0] + sacc[jb][1];
                rs1 += sacc[jb][2] + sacc[jb][3];
                int c0 = jb * 8 + 2 * t;
                Pw[pword(g, c0)]     = to_tf32f(sacc[jb][0]);
                Pw[pword(g, c0 + 1)] = to_tf32f(sacc[jb][1]);
                Pw[pword(g + 8, c0)]     = to_tf32f(sacc[jb][2]);
                Pw[pword(g + 8, c0 + 1)] = to_tf32f(sacc[jb][3]);
            }
        }
        rs0 += __shfl_xor_sync(0xffffffffu, rs0, 1);
        rs0 += __shfl_xor_sync(0xffffffffu, rs0, 2);
        rs1 += __shfl_xor_sync(0xffffffffu, rs1, 1);
        rs1 += __shfl_xor_sync(0xffffffffu, rs1, 2);
        l0 = l0 * corr0 + rs0;
        l1 = l1 * corr1 + rs1;
        #pragma unroll
        for (int nb = 0; nb < 8; nb++) {
            oacc[nb][0] *= corr0; oacc[nb][1] *= corr0;
            oacc[nb][2] *= corr1; oacc[nb][3] *= corr1;
        }
        m0 = mn0; m1 = mn1;
        __syncwarp();

        #pragma unroll
        for (int kp = 0; kp < 8; kp++) {
            if (kp < kplo || kp >= kphi) continue;
            uint32_t bfr[8][4];
            #pragma unroll
            for (int nb = 0; nb < 8; nb++)
                *(uint4*)bfr[nb] = *(const uint4*)(Vsm + (((nb << 3) + kp) << 7) + vr * 4);
            #pragma unroll
            for (int h2 = 0; h2 < 2; h2++) {
                int ks = kp * 2 + h2;
                uint32_t afr[4];
                *(uint4*)afr = *(const uint4*)(Pw + (ks << 7) + lane * 4);
                #pragma unroll
                for (int nb = 0; nb < 8; nb++)
                    mma_tf32(oacc[nb], afr, &bfr[nb][2 * h2]);
            }
        }
    }

    // ---------------- fused combine epilogue ----------------
    float inv0 = 1.f / l0, inv1 = 1.f / l1;
    size_t i0 = a * 128 + r0, i1 = i0 + 8;
    float wl0, c2_0, wl1, c2_1;
    {
        const float* lg = g_qkv + i0 * RS_ + CWOFF_ + h * 3;
        float z0 = lg[0] + bcomb[h * 3 + 0];
        float z1 = lg[1] + bcomb[h * 3 + 1];
        float z2 = lg[2] + bcomb[h * 3 + 2];
        wl0 = 1.f / (1.f + __expf(-z0)) + 1.f / (1.f + __expf(-z1));
        c2_0 = 1.f / (1.f + __expf(-z2));
    }
    {
        const float* lg = g_qkv + i1 * RS_ + CWOFF_ + h * 3;
        float z0 = lg[0] + bcomb[h * 3 + 0];
        float z1 = lg[1] + bcomb[h * 3 + 1];
        float z2 = lg[2] + bcomb[h * 3 + 2];
        wl1 = 1.f / (1.f + __expf(-z0)) + 1.f / (1.f + __expf(-z1));
        c2_1 = 1.f / (1.f + __expf(-z2));
    }
    int cbase = h * 64;
    #pragma unroll
    for (int nb = 0; nb < 8; nb++) {
        int d0 = nb * 8 + 2 * t;
        g_y[apermi((int)i0, cbase + d0,     DIM_)] = to_tf32f(wl0 * (oacc[nb][0] * inv0) + c2_0 * oc[nb][0]);
        g_y[apermi((int)i0, cbase + d0 + 1, DIM_)] = to_tf32f(wl0 * (oacc[nb][1] * inv0) + c2_0 * oc[nb][1]);
        g_y[apermi((int)i1, cbase + d0,     DIM_)] = to_tf32f(wl1 * (oacc[nb][2] * inv1) + c2_1 * oc[nb][2]);
        g_y[apermi((int)i1, cbase + d0 + 1, DIM_)] = to_tf32f(wl1 * (oacc[nb][3] * inv1) + c2_1 * oc[nb][3]);
    }
}

// ---------------- launch ----------------
extern "C" void kernel_launch(void* const* d_in, const int* in_sizes, int n_in,
                              void* d_out, int out_size) {
    const float* inp    = (const float*)d_in[0];
    const float* rms_w  = (const float*)d_in[1];
    const float* w_qkv  = (const float*)d_in[2];
    const float* k_pos  = (const float*)d_in[3];
    const float* v_pos  = (const float*)d_in[4];
    const float* kc_w   = (const float*)d_in[5];
    const float* kc_b   = (const float*)d_in[6];
    const float* vc_w   = (const float*)d_in[7];
    const float* vc_b   = (const float*)d_in[8];
    // d_in[9] = mem_kv: provably unused (always masked)
    const float* w_comb = (const float*)d_in[10];
    const float* b_comb = (const float*)d_in[11];
    const float* w_out  = (const float*)d_in[12];
    float* out = (float*)d_out;

    const int GSMEM = 2 * 32768;   // 65536 (2-stage)
    const int CSMEM = 3 * 24576;   // 73728
    const int ASMEM = 131072;
    cudaFuncSetAttribute(k_tgemm, cudaFuncAttributeMaxDynamicSharedMemorySize, GSMEM);
    cudaFuncSetAttribute(k_tconv, cudaFuncAttributeMaxDynamicSharedMemorySize, CSMEM);
    cudaFuncSetAttribute(k_attn, cudaFuncAttributeMaxDynamicSharedMemorySize, ASMEM);

    float *px, *pwb1, *pwb2, *pqkv, *py;
    cudaGetSymbolAddress((void**)&px, g_x);
    cudaGetSymbolAddress((void**)&pwb1, g_wb1);
    cudaGetSymbolAddress((void**)&pwb2, g_wb2);
    cudaGetSymbolAddress((void**)&pqkv, g_qkv);
    cudaGetSymbolAddress((void**)&py, g_y);

    dim3 tb(32, 8);
    k_rmsnorm<<<S_, 256>>>(inp, rms_w);
    k_prepbt<<<dim3(RS_ / 32, DIM_ / 32), tb>>>(w_qkv, 6144, w_comb, 96, pwb1);
    k_prepbt<<<dim3(DIM_ / 32, DIM_ / 32), tb>>>(w_out, 2048, (const float*)0, 0, pwb2);
    k_prepw<<<dim3(64, 64), 256>>>(kc_w, vc_w);
    k_tgemm<<<dim3(RS_ / 128, S_ / 128), 128, GSMEM>>>(px, pwb1, pqkv, RS_, DIM_);
    k_addpos<<<dim3(128, 64), 256>>>(k_pos, v_pos);
    k_tconv<<<dim3(KSPLIT_, 64), 256, CSMEM>>>();
    k_convred<<<512, 256>>>(kc_b, vc_b);
    k_attn<<<dim3(64, 32), 256, ASMEM>>>(b_comb);
    k_tgemm<<<dim3(DIM_ / 128, S_ / 128), 128, GSMEM>>>(py, pwb2, out, DIM_, DIM_);
}

// round 15
// speedup vs baseline: 1.4601x; 1.4601x over previous
#include <cuda_runtime.h>
#include <cstdint>
#include <math.h>

// ---------------- constants ----------------
#define S_    8192
#define DIM_  2048
#define H_    32
#define DH_   64
#define CBS_  64
#define NC_   128          // S/CBS
#define RS_   6272         // fused GEMM width: 6144 qkv + 96 comb + 32 pad (49*128)
#define KOFF_ 2048
#define VOFF_ 4096
#define CWOFF_ 6144
#define SCALE_ 0.125f
#define KSPLIT_ 4
#define NEGINF_ (-3.402823466e38f)
#define RMS_EPS_ 1.1920929e-07f

// ---------------- scratch ----------------
__device__ float g_x[S_ * DIM_];                      // rms-normed input (A-perm, tf32)
__device__ float g_wb1[RS_ * DIM_];                   // [wqkv|wcomb|0]^T (B-perm, tf32)
__device__ float g_wb2[DIM_ * DIM_];                  // w_out^T          (B-perm, tf32)
__device__ float g_y[S_ * DIM_];                      // combined branches (A-perm, tf32)
__device__ float g_qkv[S_ * RS_];                     // q|k|v|comb-logits (row-major)
__device__ float g_ap[64 * 128 * 4096];               // conv A (A-perm tf32)
__device__ float g_wtp[64 * 64 * 4096];               // conv W (B-perm tf32)
__device__ float g_part[2][KSPLIT_][H_ * NC_ * DH_];  // conv split-K partials
__device__ float g_ckv[2][H_ * NC_ * DH_];            // compressed k / v

// ================= PTX helpers =================
__device__ __forceinline__ uint32_t smem_u32(const void* p) {
    uint32_t a;
    asm("{ .reg .u64 t; cvta.to.shared.u64 t, %1; cvt.u32.u64 %0, t; }" : "=r"(a) : "l"(p));
    return a;
}
#define CP_ASYNC16(so, g) asm volatile("cp.async.cg.shared.global [%0], [%1], 16;" :: "r"(so), "l"(g) : "memory")
#define CP_COMMIT()  asm volatile("cp.async.commit_group;" ::: "memory")
#define CP_WAIT1()   asm volatile("cp.async.wait_group 1;" ::: "memory")

__device__ __forceinline__ float to_tf32f(float x) {
    uint32_t u;
    asm("cvt.rna.tf32.f32 %0, %1;" : "=r"(u) : "f"(x));
    return __uint_as_float(u);
}
__device__ __forceinline__ void mma_tf32(float* c, const uint32_t* a, const uint32_t* b) {
    asm volatile("mma.sync.aligned.m16n8k8.row.col.f32.tf32.tf32.f32 "
                 "{%0,%1,%2,%3},{%4,%5,%6,%7},{%8,%9},{%0,%1,%2,%3};"
                 : "+f"(c[0]), "+f"(c[1]), "+f"(c[2]), "+f"(c[3])
                 : "r"(a[0]), "r"(a[1]), "r"(a[2]), "r"(a[3]), "r"(b[0]), "r"(b[1]));
}

// permuted index helpers (float index)
__device__ __forceinline__ size_t apermi(int m, int k, int K) {
    int lane = ((m & 7) << 2) + (k & 3);
    int e = ((m >> 3) & 1) | (((k >> 2) & 1) << 1);
    return ((((size_t)(m >> 4)) * (K >> 3) + (k >> 3)) << 7) + (lane << 2) + e;
}
__device__ __forceinline__ size_t bpermi(int n, int k, int K) {
    int lane = ((n & 7) << 2) + (k & 3);
    int e = (k >> 2) & 3;
    return ((((size_t)(n >> 3)) * (K >> 4) + (k >> 4)) << 7) + (lane << 2) + e;
}
// P A-perm word within a 16-row warp tile (cols = kv)
__device__ __forceinline__ int pword(int m, int c) {
    return ((c >> 3) << 7) + (((m & 7) << 2) + (c & 3)) * 4 + ((m >> 3) & 1) + (((c >> 2) & 1) << 1);
}
__device__ __forceinline__ int vrot(int l) { return ((l & 3) << 3) | (l >> 2); }

// ====== tf32 tensor-core GEMM: CTA 128x128, 4 warps (64x64), 3 stages, 2 CTAs/SM ======
__global__ __launch_bounds__(128, 2) void k_tgemm(const float* __restrict__ A,
                                                  const float* __restrict__ B,
                                                  float* __restrict__ C, int N, int K) {
    extern __shared__ float sm[];
    const uint32_t sbase = smem_u32(sm);
    const int tid = threadIdx.x;
    const int wid = tid >> 5, lane = tid & 31;
    const int g = lane >> 2, t = lane & 3;
    const int bm = blockIdx.y * 128, bn = blockIdx.x * 128;
    const int mbw = (wid >> 1) * 4;
    const int nbw = (wid & 1) * 8;
    const int KB8 = K >> 3, KB16 = K >> 4;
    const int NK = K >> 5;

    float acc[4][8][4];
    #pragma unroll
    for (int i = 0; i < 4; i++)
        #pragma unroll
        for (int j = 0; j < 8; j++)
            #pragma unroll
            for (int e = 0; e < 4; e++) acc[i][j][e] = 0.f;

    auto load_stage = [&](int kt, int s) {
        #pragma unroll
        for (int it = 0; it < 16; it++) {
            int seg = tid + it * 128;
            int blk = (seg >> 5) & 31;
            int w16 = seg & 31;
            const float* gp;
            if (seg < 1024) {
                int mbl = blk >> 2, kbl = blk & 3;
                gp = A + ((((size_t)(bm >> 4) + mbl) * KB8 + (kt << 2) + kbl) << 7) + (w16 << 2);
            } else {
                int nbl = blk >> 1, kbl = blk & 1;
                gp = B + ((((size_t)(bn >> 3) + nbl) * KB16 + (kt << 1) + kbl) << 7) + (w16 << 2);
            }
            uint32_t so = sbase + s * 32768 + (seg << 4);
            CP_ASYNC16(so, gp);
        }
        CP_COMMIT();
    };

    load_stage(0, 0);
    load_stage(1, 1);

    for (int kt = 0; kt < NK; kt++) {
        int s = kt - (kt / 3) * 3;
        CP_WAIT1();
        __syncthreads();
        if (kt + 2 < NK) {
            int s2 = (kt + 2) - ((kt + 2) / 3) * 3;
            load_stage(kt + 2, s2);
        } else CP_COMMIT();
        const float* As = sm + s * 8192;
        const float* Bs = As + 4096;
        #pragma unroll
        for (int kp = 0; kp < 2; kp++) {
            uint32_t bfr[8][4];
            #pragma unroll
            for (int j = 0; j < 8; j++)
                *(uint4*)bfr[j] = *(const uint4*)(Bs + (((nbw + j) << 1) + kp) * 128 + (lane << 2));
            #pragma unroll
            for (int h2 = 0; h2 < 2; h2++) {
                int ks = kp * 2 + h2;
                uint32_t afr[4][4];
                #pragma unroll
                for (int i = 0; i < 4; i++)
                    *(uint4*)afr[i] = *(const uint4*)(As + (((mbw + i) << 2) + ks) * 128 + (lane << 2));
                #pragma unroll
                for (int i = 0; i < 4; i++)
                    #pragma unroll
                    for (int j = 0; j < 8; j++) mma_tf32(acc[i][j], afr[i], &bfr[j][2 * h2]);
            }
        }
    }

    #pragma unroll
    for (int i = 0; i < 4; i++)
        #pragma unroll
        for (int j = 0; j < 8; j++) {
            int row = bm + (mbw + i) * 16 + g;
            int col = bn + (nbw + j) * 8 + 2 * t;
            *(float2*)(C + (size_t)row * N + col) = make_float2(acc[i][j][0], acc[i][j][1]);
            *(float2*)(C + (size_t)(row + 8) * N + col) = make_float2(acc[i][j][2], acc[i][j][3]);
        }
}

// ================= conv as tensor-core GEMM, split-K=4 =====================
__global__ __launch_bounds__(256, 2) void k_tconv() {
    extern __shared__ float sm[];
    const uint32_t sbase = smem_u32(sm);
    const int tid = threadIdx.x;
    const int wid = tid >> 5, lane = tid & 31;
    const int g = lane >> 2, t = lane & 3;
    const int ksp = blockIdx.x;
    const int b = blockIdx.y;
    const float* A = g_ap + (size_t)b * 524288;
    const float* B = g_wtp + (size_t)b * 262144;
    const int mbw = (wid >> 1) * 2;
    const int nbw = (wid & 1) * 4;

    float acc[2][4][4];
    #pragma unroll
    for (int i = 0; i < 2; i++)
        #pragma unroll
        for (int j = 0; j < 4; j++)
            #pragma unroll
            for (int e = 0; e < 4; e++) acc[i][j][e] = 0.f;

    auto load_stage = [&](int kt, int s) {
        #pragma unroll
        for (int it = 0; it < 6; it++) {
            int seg = tid + it * 256;
            const float* gp;
            uint32_t so;
            if (seg < 1024) {
                int blk = seg >> 5, w16 = seg & 31;
                int mbl = blk >> 2, kbl = blk & 3;
                gp = A + (((size_t)mbl * 512 + (kt << 2) + kbl) << 7) + (w16 << 2);
                so = sbase + s * 24576 + (seg << 4);
            } else {
                int sb = seg - 1024;
                int blk = sb >> 5, w16 = sb & 31;
                int nbl = blk >> 1, kbl = blk & 1;
                gp = B + (((size_t)nbl * 256 + (kt << 1) + kbl) << 7) + (w16 << 2);
                so = sbase + s * 24576 + 16384 + (sb << 4);
            }
            CP_ASYNC16(so, gp);
        }
        CP_COMMIT();
    };

    const int kt0 = ksp * 32;
    load_stage(kt0, 0);
    load_stage(kt0 + 1, 1);

    for (int kk = 0; kk < 32; kk++) {
        int s = kk - (kk / 3) * 3;
        CP_WAIT1();
        __syncthreads();
        if (kk + 2 < 32) {
            int s2 = (kk + 2) - ((kk + 2) / 3) * 3;
            load_stage(kt0 + kk + 2, s2);
        } else CP_COMMIT();
        const float* As = sm + s * 6144;
        const float* Bs = As + 4096;
        #pragma unroll
        for (int kp = 0; kp < 2; kp++) {
            uint32_t bfr[4][4];
            #pragma unroll
            for (int j = 0; j < 4; j++)
                *(uint4*)bfr[j] = *(const uint4*)(Bs + (((nbw + j) << 1) + kp) * 128 + (lane << 2));
            #pragma unroll
            for (int h2 = 0; h2 < 2; h2++) {
                int ks4 = kp * 2 + h2;
                uint32_t afr[2][4];
                #pragma unroll
                for (int i = 0; i < 2; i++)
                    *(uint4*)afr[i] = *(const uint4*)(As + (((mbw + i) << 2) + ks4) * 128 + (lane << 2));
                #pragma unroll
                for (int i = 0; i < 2; i++)
                    #pragma unroll
                    for (int j = 0; j < 4; j++) mma_tf32(acc[i][j], afr[i], &bfr[j][2 * h2]);
            }
        }
    }

    int kv = b >> 5, h = b & 31;
    float* out = g_part[kv][ksp] + h * 8192;
    #pragma unroll
    for (int i = 0; i < 2; i++)
        #pragma unroll
        for (int j = 0; j < 4; j++) {
            int row = (mbw + i) * 16 + g;
            int col = (nbw + j) * 8 + 2 * t;
            *(float2*)(out + row * 64 + col) = make_float2(acc[i][j][0], acc[i][j][1]);
            *(float2*)(out + (row + 8) * 64 + col) = make_float2(acc[i][j][2], acc[i][j][3]);
        }
}

// ---------------- conv A build (vectorized) ----------------
__global__ void k_addpos(const float* __restrict__ kpos, const float* __restrict__ vpos) {
    int n = blockIdx.x;
    int b = blockIdx.y;
    int kv = b >> 5, h = b & 31;
    const float* pos = (kv ? vpos : kpos) + h * 4096;
    const int coloff = (kv ? VOFF_ : KOFF_) + h * 64;
    float* dst = g_ap + (size_t)b * 524288;
    const int lb = (n & 7) << 2;
    const int e0 = (n >> 3) & 1;
    for (int q = threadIdx.x; q < 1024; q += 256) {
        int c = q << 2;
        int t = c >> 6, i = c & 63;
        float4 a4 = *(const float4*)(g_qkv + (size_t)(n * 64 + t) * RS_ + coloff + i);
        float4 p4 = *(const float4*)(pos + c);
        float vals[4] = {a4.x + p4.x, a4.y + p4.y, a4.z + p4.z, a4.w + p4.w};
        int e = e0 | (((c >> 2) & 1) << 1);
        float* dstb = dst + ((((size_t)(n >> 4)) * 512 + (c >> 3)) << 7) + e;
        #pragma unroll
        for (int s = 0; s < 4; s++)
            dstb[(lb + s) << 2] = to_tf32f(vals[s]);
    }
}

// ---------------- conv weights -> B-perm tf32 ----------------
__global__ void k_prepw(const float* __restrict__ kcw, const float* __restrict__ vcw) {
    __shared__ float ts[64 * 65];
    int o = blockIdx.x;
    int b = blockIdx.y;
    int kv = b >> 5, h = b & 31;
    const float* src = (kv ? vcw : kcw) + (size_t)(h * 64 + o) * 4096;
    float* dst = g_wtp + (size_t)b * 262144;
    int tid = threadIdx.x;
    #pragma unroll
    for (int rep = 0; rep < 16; rep++) {
        int i = rep * 4 + (tid >> 6);
        int t = tid & 63;
        ts[t * 65 + i] = src[i * 64 + t];
    }
    __syncthreads();
    #pragma unroll
    for (int rep = 0; rep < 16; rep++) {
        int kappa = rep * 256 + tid;
        int t = kappa >> 6, i = kappa & 63;
        dst[bpermi(o, kappa, 4096)] = to_tf32f(ts[t * 65 + i]);
    }
}

// ---------------- rms norm -> A-perm tf32 ----------------
__global__ void k_rmsnorm(const float* __restrict__ inp, const float* __restrict__ w) {
    int row = blockIdx.x;
    const float* p = inp + (size_t)row * DIM_;
    float ss = 0.f;
    for (int c = threadIdx.x; c < DIM_; c += 256) { float v = p[c]; ss += v * v; }
    #pragma unroll
    for (int o = 16; o > 0; o >>= 1) ss += __shfl_xor_sync(0xffffffffu, ss, o);
    __shared__ float red[8];
    __shared__ float scs;
    if ((threadIdx.x & 31) == 0) red[threadIdx.x >> 5] = ss;
    __syncthreads();
    if (threadIdx.x == 0) {
        float tt = 0.f;
        #pragma unroll
        for (int v = 0; v < 8; v++) tt += red[v];
        scs = rsqrtf(tt * (1.f / (float)DIM_) + RMS_EPS_);
    }
    __syncthreads();
    float sc = scs;
    for (int c = threadIdx.x; c < DIM_; c += 256)
        g_x[apermi(row, c, DIM_)] = to_tf32f(p[c] * sc * w[c]);
}

// ---------------- transpose + concat -> B-perm tf32 ----------------
__global__ void k_prepbt(const float* __restrict__ s0, int c0,
                         const float* __restrict__ s1, int c1,
                         float* __restrict__ o) {
    __shared__ float t[32][33];
    int nt = blockIdx.x * 32, kt = blockIdx.y * 32;
    int tx = threadIdx.x, ty = threadIdx.y;
    #pragma unroll
    for (int r = ty; r < 32; r += 8) {
        int k = kt + r, n = nt + tx;
        float v = 0.f;
        if (n < c0) v = s0[(size_t)k * c0 + n];
        else if (s1 && n < c0 + c1) v = s1[(size_t)k * c1 + (n - c0)];
        t[r][tx] = v;
    }
    __syncthreads();
    #pragma unroll
    for (int r = ty; r < 32; r += 8) {
        int n = nt + r, k = kt + tx;
        o[bpermi(n, k, 2048)] = to_tf32f(t[tx][r]);
    }
}

// ---------------- conv split-K reduce + bias (vectorized) ----------------
__global__ void k_convred(const float* __restrict__ kcb, const float* __restrict__ vcb) {
    int idx = blockIdx.x * 256 + threadIdx.x;
    const int per4 = (H_ * NC_ * DH_) >> 2;
    if (idx >= 2 * per4) return;
    int kv = idx / per4;
    int rem = idx - kv * per4;
    float4 s = *(const float4*)(&g_part[kv][0][rem << 2]);
    #pragma unroll
    for (int ks = 1; ks < KSPLIT_; ks++) {
        float4 p = *(const float4*)(&g_part[kv][ks][rem << 2]);
        s.x += p.x; s.y += p.y; s.z += p.z; s.w += p.w;
    }
    int elem = rem << 2;
    int h = elem >> 13;
    int o = elem & 63;
    float4 bia = *(const float4*)((kv ? vcb : kcb) + h * 64 + o);
    s.x += bia.x; s.y += bia.y; s.z += bia.z; s.w += bia.w;
    *(float4*)(&g_ckv[kv][elem]) = s;
}

// ---- vectorized fills: K (LDG.128 + 4 rotated STS.32), V (4 LDG.32 + STS.128) ----
__device__ __forceinline__ void fill_k(float* Ksm, const float* rowbase, size_t rowstride,
                                       int tid) {
    #pragma unroll
    for (int it = 0; it < 8; it++) {
        int f = tid + it * 256;
        int kv = f >> 4, q = f & 15;
        float4 v4 = *(const float4*)(rowbase + (size_t)kv * rowstride + 4 * q);
        float vals[4] = {v4.x, v4.y, v4.z, v4.w};
        float* dstb = Ksm + ((((kv >> 3) << 2) + (q >> 2)) << 7) + (q & 3);
        int lb = (kv & 7) << 2;
        #pragma unroll
        for (int s = 0; s < 4; s++) {
            int c = (s + (q >> 2)) & 3;
            dstb[(lb + c) << 2] = to_tf32f(vals[c]);
        }
    }
}
__device__ __forceinline__ void fill_v(float* Vsm, const float* rowbase, size_t rowstride,
                                       int tid) {
    #pragma unroll
    for (int it = 0; it < 8; it++) {
        int f = tid + it * 256;
        int d = f & 63, rem = f >> 6;
        int kv16 = rem >> 2, kvlow = rem & 3;
        int kvb = (kv16 << 4) + kvlow;
        const float* s0 = rowbase + (size_t)kvb * rowstride + d;
        float4 o;
        o.x = to_tf32f(s0[0]);
        o.y = to_tf32f(s0[4 * rowstride]);
        o.z = to_tf32f(s0[8 * rowstride]);
        o.w = to_tf32f(s0[12 * rowstride]);
        int lane = (kvlow << 3) + (d & 7);
        *(float4*)(Vsm + ((((d >> 3) << 3) + kv16) << 7) + (lane << 2)) = o;
    }
}

// ===== merged attention: compressed (regs) + local (online) + fused combine =====
__global__ __launch_bounds__(256, 1) void k_attn(const float* __restrict__ bcomb) {
    extern __shared__ float smA[];
    float* Ksm = smA;
    float* Vsm = smA + 8192;
    float* Psm = smA + 16384;
    int a = blockIdx.x, h = blockIdx.y;
    int tid = threadIdx.x, w = tid >> 5, lane = tid & 31;
    int g = lane >> 2, t = lane & 3;
    int r0 = w * 16 + g, r1 = r0 + 8;
    int vr = vrot(lane);
    float* Pw = Psm + w * 2048;

    uint32_t qfr[8][4];
    {
        const float* qb = g_qkv + (size_t)(a * 128 + w * 16) * RS_ + h * 64;
        #pragma unroll
        for (int ks = 0; ks < 8; ks++) {
            qfr[ks][0] = __float_as_uint(to_tf32f(qb[(size_t)g * RS_ + ks * 8 + t]));
            qfr[ks][1] = __float_as_uint(to_tf32f(qb[(size_t)(g + 8) * RS_ + ks * 8 + t]));
            qfr[ks][2] = __float_as_uint(to_tf32f(qb[(size_t)g * RS_ + ks * 8 + t + 4]));
            qfr[ks][3] = __float_as_uint(to_tf32f(qb[(size_t)(g + 8) * RS_ + ks * 8 + t + 4]));
        }
    }

    // ---------------- phase C: compressed branch -> oc (normalized) --------------
    float oc[8][4];
    {
        const int qskip = a >> 4;
        const int kpskip = a >> 3;
        fill_k(Ksm, g_ckv[0] + h * 8192, 64, tid);
        fill_v(Vsm, g_ckv[1] + h * 8192, 64, tid);
        __syncthreads();

        float sacc[16][4];
        #pragma unroll
        for (int jb = 0; jb < 16; jb++)
            #pragma unroll
            for (int e = 0; e < 4; e++) sacc[jb][e] = 0.f;
        #pragma unroll
        for (int qq = 0; qq < 4; qq++) {
            if (qq < qskip) continue;
            #pragma unroll
            for (int kp = 0; kp < 4; kp++) {
                uint32_t bfr[4][4];
                #pragma unroll
                for (int j = 0; j < 4; j++)
                    *(uint4*)bfr[j] = *(const uint4*)(Ksm + ((((qq * 4 + j) << 2) + kp) << 7) + lane * 4);
                #pragma unroll
                for (int h2 = 0; h2 < 2; h2++) {
                    int ks = kp * 2 + h2;
                    #pragma unroll
                    for (int j = 0; j < 4; j++)
                        mma_tf32(sacc[qq * 4 + j], qfr[ks], &bfr[j][2 * h2]);
                }
            }
        }

        int th0 = (a * 128 + r0) >> 6;
        int th1 = (a * 128 + r1) >> 6;
        float mx0 = NEGINF_, mx1 = NEGINF_;
        #pragma unroll
        for (int qq = 0; qq < 4; qq++) {
            if (qq < qskip) continue;
            #pragma unroll
            for (int j = 0; j < 4; j++) {
                int jb = qq * 4 + j;
                int c0 = jb * 8 + 2 * t, c1 = c0 + 1;
                sacc[jb][0] = (c0 >= th0) ? sacc[jb][0] * SCALE_ : NEGINF_;
                sacc[jb][1] = (c1 >= th0) ? sacc[jb][1] * SCALE_ : NEGINF_;
                sacc[jb][2] = (c0 >= th1) ? sacc[jb][2] * SCALE_ : NEGINF_;
                sacc[jb][3] = (c1 >= th1) ? sacc[jb][3] * SCALE_ : NEGINF_;
                mx0 = fmaxf(mx0, fmaxf(sacc[jb][0], sacc[jb][1]));
                mx1 = fmaxf(mx1, fmaxf(sacc[jb][2], sacc[jb][3]));
            }
        }
        mx0 = fmaxf(mx0, __shfl_xor_sync(0xffffffffu, mx0, 1));
        mx0 = fmaxf(mx0, __shfl_xor_sync(0xffffffffu, mx0, 2));
        mx1 = fmaxf(mx1, __shfl_xor_sync(0xffffffffu, mx1, 1));
        mx1 = fmaxf(mx1, __shfl_xor_sync(0xffffffffu, mx1, 2));
        float s0 = 0.f, s1 = 0.f;
        #pragma unroll
        for (int qq = 0; qq < 4; qq++) {
            if (qq < qskip) continue;
            #pragma unroll
            for (int j = 0; j < 4; j++) {
                int jb = qq * 4 + j;
                sacc[jb][0] = __expf(sacc[jb][0] - mx0);
                sacc[jb][1] = __expf(sacc[jb][1] - mx0);
                sacc[jb][2] = __expf(sacc[jb][2] - mx1);
                sacc[jb][3] = __expf(sacc[jb][3] - mx1);
                s0 += sacc[jb][0] + sacc[jb][1];
                s1 += sacc[jb][2] + sacc[jb][3];
                int c0 = jb * 8 + 2 * t;
                Pw[pword(g, c0)]     = to_tf32f(sacc[jb][0]);
                Pw[pword(g, c0 + 1)] = to_tf32f(sacc[jb][1]);
                Pw[pword(g + 8, c0)]     = to_tf32f(sacc[jb][2]);
                Pw[pword(g + 8, c0 + 1)] = to_tf32f(sacc[jb][3]);
            }
        }
        s0 += __shfl_xor_sync(0xffffffffu, s0, 1);
        s0 += __shfl_xor_sync(0xffffffffu, s0, 2);
        s1 += __shfl_xor_sync(0xffffffffu, s1, 1);
        s1 += __shfl_xor_sync(0xffffffffu, s1, 2);
        __syncwarp();

        #pragma unroll
        for (int nb = 0; nb < 8; nb++)
            #pragma unroll
            for (int e = 0; e < 4; e++) oc[nb][e] = 0.f;
        #pragma unroll
        for (int kp = 0; kp < 8; kp++) {
            if (kp < kpskip) continue;
            uint32_t bfr[8][4];
            #pragma unroll
            for (int nb = 0; nb < 8; nb++)
                *(uint4*)bfr[nb] = *(const uint4*)(Vsm + (((nb << 3) + kp) << 7) + vr * 4);
            #pragma unroll
            for (int h2 = 0; h2 < 2; h2++) {
                int ks = kp * 2 + h2;
                uint32_t afr[4];
                *(uint4*)afr = *(const uint4*)(Pw + (ks << 7) + lane * 4);
                #pragma unroll
                for (int nb = 0; nb < 8; nb++)
                    mma_tf32(oc[nb], afr, &bfr[nb][2 * h2]);
            }
        }
        float inv0 = 1.f / s0, inv1 = 1.f / s1;
        #pragma unroll
        for (int nb = 0; nb < 8; nb++) {
            oc[nb][0] *= inv0; oc[nb][1] *= inv0;
            oc[nb][2] *= inv1; oc[nb][3] *= inv1;
        }
    }

    // ---------------- phase L: local branch (online over 2 tiles) ----------------
    float m0 = NEGINF_, m1 = NEGINF_, l0 = 0.f, l1 = 0.f;
    float oacc[8][4];
    #pragma unroll
    for (int nb = 0; nb < 8; nb++)
        #pragma unroll
        for (int e = 0; e < 4; e++) oacc[nb][e] = 0.f;
    int tstart = (a == 0) ? 1 : 0;

    for (int tile = tstart; tile < 2; tile++) {
        __syncthreads();
        int jbase = (a - 1 + tile) * 128;
        {
            const float* kb = g_qkv + (size_t)jbase * RS_ + KOFF_ + h * 64;
            const float* vb = g_qkv + (size_t)jbase * RS_ + VOFF_ + h * 64;
            fill_k(Ksm, kb, RS_, tid);
            fill_v(Vsm, vb, RS_, tid);
        }
        __syncthreads();

        int qlo = (tile == 0) ? (w >> 1) : 0;
        int qhi = (tile == 0) ? 4 : ((w >> 1) + 1);
        int kplo = (tile == 0) ? w : 0;
        int kphi = (tile == 0) ? 8 : (w + 1);

        float sacc[16][4];
        #pragma unroll
        for (int jb = 0; jb < 16; jb++)
            #pragma unroll
            for (int e = 0; e < 4; e++) sacc[jb][e] = 0.f;
        #pragma unroll
        for (int qq = 0; qq < 4; qq++) {
            if (qq < qlo || qq >= qhi) continue;
            #pragma unroll
            for (int kp = 0; kp < 4; kp++) {
                uint32_t bfr[4][4];
                #pragma unroll
                for (int j = 0; j < 4; j++)
                    *(uint4*)bfr[j] = *(const uint4*)(Ksm + ((((qq * 4 + j) << 2) + kp) << 7) + lane * 4);
                #pragma unroll
                for (int h2 = 0; h2 < 2; h2++) {
                    int ks = kp * 2 + h2;
                    #pragma unroll
                    for (int j = 0; j < 4; j++)
                        mma_tf32(sacc[qq * 4 + j], qfr[ks], &bfr[j][2 * h2]);
                }
            }
        }

        float rm0 = NEGINF_, rm1 = NEGINF_;
        #pragma unroll
        for (int qq = 0; qq < 4; qq++) {
            if (qq < qlo || qq >= qhi) continue;
            #pragma unroll
            for (int j = 0; j < 4; j++) {
                int jb = qq * 4 + j;
                int c0 = jb * 8 + 2 * t, c1 = c0 + 1;
                bool a00, a01, a10, a11;
                if (tile == 0) { a00 = c0 >= r0; a01 = c1 >= r0; a10 = c0 >= r1; a11 = c1 >= r1; }
                else           { a00 = c0 <= r0; a01 = c1 <= r0; a10 = c0 <= r1; a11 = c1 <= r1; }
                sacc[jb][0] = a00 ? sacc[jb][0] * SCALE_ : NEGINF_;
                sacc[jb][1] = a01 ? sacc[jb][1] * SCALE_ : NEGINF_;
                sacc[jb][2] = a10 ? sacc[jb][2] * SCALE_ : NEGINF_;
                sacc[jb][3] = a11 ? sacc[jb][3] * SCALE_ : NEGINF_;
                rm0 = fmaxf(rm0, fmaxf(sacc[jb][0], sacc[jb][1]));
                rm1 = fmaxf(rm1, fmaxf(sacc[jb][2], sacc[jb][3]));
            }
        }
        rm0 = fmaxf(rm0, __shfl_xor_sync(0xffffffffu, rm0, 1));
        rm0 = fmaxf(rm0, __shfl_xor_sync(0xffffffffu, rm0, 2));
        rm1 = fmaxf(rm1, __shfl_xor_sync(0xffffffffu, rm1, 1));
        rm1 = fmaxf(rm1, __shfl_xor_sync(0xffffffffu, rm1, 2));
        float mn0 = fmaxf(m0, rm0), mn1 = fmaxf(m1, rm1);
        float corr0 = __expf(m0 - mn0), corr1 = __expf(m1 - mn1);
        float rs0 = 0.f, rs1 = 0.f;
        #pragma unroll
        for (int qq = 0; qq < 4; qq++) {
            if (qq < qlo || qq >= qhi) continue;
            #pragma unroll
            for (int j = 0; j < 4; j++) {
                int jb = qq * 4 + j;
                sacc[jb][0] = __expf(sacc[jb][0] - mn0);
                sacc[jb][1] = __expf(sacc[jb][1] - mn0);
                sacc[jb][2] = __expf(sacc[jb][2] - mn1);
                sacc[jb][3] = __expf(sacc[jb][3] - mn1);
                rs0 += sacc[jb][0] + sacc[jb][1];
                rs1 += sacc[jb][2] + sacc[jb][3];
                int c0 = jb * 8 + 2 * t;
                Pw[pword(g, c0)]     = to_tf32f(sacc[jb][0]);
                Pw[pword(g, c0 + 1)] = to_tf32f(sacc[jb][1]);
                Pw[pword(g + 8, c0)]     = to_tf32f(sacc[jb][2]);
                Pw[pword(g + 8, c0 + 1)] = to_tf32f(sacc[jb][3]);
            }
        }
        rs0 += __shfl_xor_sync(0xffffffffu, rs0, 1);
        rs0 += __shfl_xor_sync(0xffffffffu, rs0, 2);
        rs1 += __shfl_xor_sync(0xffffffffu, rs1, 1);
        rs1 += __shfl_xor_sync(0xffffffffu, rs1, 2);
        l0 = l0 * corr0 + rs0;
        l1 = l1 * corr1 + rs1;
        #pragma unroll
        for (int nb = 0; nb < 8; nb++) {
            oacc[nb][0] *= corr0; oacc[nb][1] *= corr0;
            oacc[nb][2] *= corr1; oacc[nb][3] *= corr1;
        }
        m0 = mn0; m1 = mn1;
        __syncwarp();

        #pragma unroll
        for (int kp = 0; kp < 8; kp++) {
            if (kp < kplo || kp >= kphi) continue;
            uint32_t bfr[8][4];
            #pragma unroll
            for (int nb = 0; nb < 8; nb++)
                *(uint4*)bfr[nb] = *(const uint4*)(Vsm + (((nb << 3) + kp) << 7) + vr * 4);
            #pragma unroll
            for (int h2 = 0; h2 < 2; h2++) {
                int ks = kp * 2 + h2;
                uint32_t afr[4];
                *(uint4*)afr = *(const uint4*)(Pw + (ks << 7) + lane * 4);
                #pragma unroll
                for (int nb = 0; nb < 8; nb++)
                    mma_tf32(oacc[nb], afr, &bfr[nb][2 * h2]);
            }
        }
    }

    // ---------------- fused combine epilogue ----------------
    float inv0 = 1.f / l0, inv1 = 1.f / l1;
    size_t i0 = a * 128 + r0, i1 = i0 + 8;
    float wl0, c2_0, wl1, c2_1;
    {
        const float* lg = g_qkv + i0 * RS_ + CWOFF_ + h * 3;
        float z0 = lg[0] + bcomb[h * 3 + 0];
        float z1 = lg[1] + bcomb[h * 3 + 1];
        float z2 = lg[2] + bcomb[h * 3 + 2];
        wl0 = 1.f / (1.f + __expf(-z0)) + 1.f / (1.f + __expf(-z1));
        c2_0 = 1.f / (1.f + __expf(-z2));
    }
    {
        const float* lg = g_qkv + i1 * RS_ + CWOFF_ + h * 3;
        float z0 = lg[0] + bcomb[h * 3 + 0];
        float z1 = lg[1] + bcomb[h * 3 + 1];
        float z2 = lg[2] + bcomb[h * 3 + 2];
        wl1 = 1.f / (1.f + __expf(-z0)) + 1.f / (1.f + __expf(-z1));
        c2_1 = 1.f / (1.f + __expf(-z2));
    }
    int cbase = h * 64;
    #pragma unroll
    for (int nb = 0; nb < 8; nb++) {
        int d0 = nb * 8 + 2 * t;
        g_y[apermi((int)i0, cbase + d0,     DIM_)] = to_tf32f(wl0 * (oacc[nb][0] * inv0) + c2_0 * oc[nb][0]);
        g_y[apermi((int)i0, cbase + d0 + 1, DIM_)] = to_tf32f(wl0 * (oacc[nb][1] * inv0) + c2_0 * oc[nb][1]);
        g_y[apermi((int)i1, cbase + d0,     DIM_)] = to_tf32f(wl1 * (oacc[nb][2] * inv1) + c2_1 * oc[nb][2]);
        g_y[apermi((int)i1, cbase + d0 + 1, DIM_)] = to_tf32f(wl1 * (oacc[nb][3] * inv1) + c2_1 * oc[nb][3]);
    }
}

// ---------------- launch ----------------
extern "C" void kernel_launch(void* const* d_in, const int* in_sizes, int n_in,
                              void* d_out, int out_size) {
    const float* inp    = (const float*)d_in[0];
    const float* rms_w  = (const float*)d_in[1];
    const float* w_qkv  = (const float*)d_in[2];
    const float* k_pos  = (const float*)d_in[3];
    const float* v_pos  = (const float*)d_in[4];
    const float* kc_w   = (const float*)d_in[5];
    const float* kc_b   = (const float*)d_in[6];
    const float* vc_w   = (const float*)d_in[7];
    const float* vc_b   = (const float*)d_in[8];
    // d_in[9] = mem_kv: provably unused (always masked)
    const float* w_comb = (const float*)d_in[10];
    const float* b_comb = (const float*)d_in[11];
    const float* w_out  = (const float*)d_in[12];
    float* out = (float*)d_out;

    const int GSMEM = 3 * 32768;   // 98304 (3-stage, proven)
    const int CSMEM = 3 * 24576;   // 73728
    const int ASMEM = 131072;
    cudaFuncSetAttribute(k_tgemm, cudaFuncAttributeMaxDynamicSharedMemorySize, GSMEM);
    cudaFuncSetAttribute(k_tconv, cudaFuncAttributeMaxDynamicSharedMemorySize, CSMEM);
    cudaFuncSetAttribute(k_attn, cudaFuncAttributeMaxDynamicSharedMemorySize, ASMEM);

    float *px, *pwb1, *pwb2, *pqkv, *py;
    cudaGetSymbolAddress((void**)&px, g_x);
    cudaGetSymbolAddress((void**)&pwb1, g_wb1);
    cudaGetSymbolAddress((void**)&pwb2, g_wb2);
    cudaGetSymbolAddress((void**)&pqkv, g_qkv);
    cudaGetSymbolAddress((void**)&py, g_y);

    dim3 tb(32, 8);
    k_rmsnorm<<<S_, 256>>>(inp, rms_w);
    k_prepbt<<<dim3(RS_ / 32, DIM_ / 32), tb>>>(w_qkv, 6144, w_comb, 96, pwb1);
    k_prepbt<<<dim3(DIM_ / 32, DIM_ / 32), tb>>>(w_out, 2048, (const float*)0, 0, pwb2);
    k_prepw<<<dim3(64, 64), 256>>>(kc_w, vc_w);
    k_tgemm<<<dim3(RS_ / 128, S_ / 128), 128, GSMEM>>>(px, pwb1, pqkv, RS_, DIM_);
    k_addpos<<<dim3(128, 64), 256>>>(k_pos, v_pos);
    k_tconv<<<dim3(KSPLIT_, 64), 256, CSMEM>>>();
    k_convred<<<512, 256>>>(kc_b, vc_b);
    k_attn<<<dim3(64, 32), 256, ASMEM>>>(b_comb);
    k_tgemm<<<dim3(DIM_ / 128, S_ / 128), 128, GSMEM>>>(py, pwb2, out, DIM_, DIM_);
}

// round 16
// speedup vs baseline: 1.5234x; 1.0433x over previous
#include <cuda_runtime.h>
#include <cstdint>
#include <math.h>

// ---------------- constants ----------------
#define S_    8192
#define DIM_  2048
#define H_    32
#define DH_   64
#define CBS_  64
#define NC_   128          // S/CBS
#define RS_   6272         // fused GEMM width: 6144 qkv + 96 comb + 32 pad (49*128)
#define KOFF_ 2048
#define VOFF_ 4096
#define CWOFF_ 6144
#define SCALE_ 0.125f
#define KSPLIT_ 4
#define NEGINF_ (-3.402823466e38f)
#define RMS_EPS_ 1.1920929e-07f

// ---------------- scratch ----------------
__device__ float g_x[S_ * DIM_];                      // rms-normed input (A-perm, tf32)
__device__ float g_wb1[RS_ * DIM_];                   // [wqkv|wcomb|0]^T (B-perm, tf32)
__device__ float g_wb2[DIM_ * DIM_];                  // w_out^T          (B-perm, tf32)
__device__ float g_y[S_ * DIM_];                      // combined branches (A-perm, tf32)
__device__ float g_qkv[S_ * RS_];                     // q|k|v|comb-logits (row-major)
__device__ float g_ap[64 * 128 * 4096];               // conv A (A-perm tf32)
__device__ float g_wtp[64 * 64 * 4096];               // conv W (B-perm tf32)
__device__ float g_part[2][KSPLIT_][H_ * NC_ * DH_];  // conv split-K partials
__device__ float g_ckv[2][H_ * NC_ * DH_];            // compressed k / v

// ================= PTX helpers =================
__device__ __forceinline__ uint32_t smem_u32(const void* p) {
    uint32_t a;
    asm("{ .reg .u64 t; cvta.to.shared.u64 t, %1; cvt.u32.u64 %0, t; }" : "=r"(a) : "l"(p));
    return a;
}
#define CP_ASYNC16(so, g) asm volatile("cp.async.cg.shared.global [%0], [%1], 16;" :: "r"(so), "l"(g) : "memory")
#define CP_COMMIT()  asm volatile("cp.async.commit_group;" ::: "memory")
#define CP_WAIT1()   asm volatile("cp.async.wait_group 1;" ::: "memory")

__device__ __forceinline__ float to_tf32f(float x) {
    uint32_t u;
    asm("cvt.rna.tf32.f32 %0, %1;" : "=r"(u) : "f"(x));
    return __uint_as_float(u);
}
__device__ __forceinline__ void mma_tf32(float* c, const uint32_t* a, const uint32_t* b) {
    asm volatile("mma.sync.aligned.m16n8k8.row.col.f32.tf32.tf32.f32 "
                 "{%0,%1,%2,%3},{%4,%5,%6,%7},{%8,%9},{%0,%1,%2,%3};"
                 : "+f"(c[0]), "+f"(c[1]), "+f"(c[2]), "+f"(c[3])
                 : "r"(a[0]), "r"(a[1]), "r"(a[2]), "r"(a[3]), "r"(b[0]), "r"(b[1]));
}

// permuted index helpers (float index)
__device__ __forceinline__ size_t apermi(int m, int k, int K) {
    int lane = ((m & 7) << 2) + (k & 3);
    int e = ((m >> 3) & 1) | (((k >> 2) & 1) << 1);
    return ((((size_t)(m >> 4)) * (K >> 3) + (k >> 3)) << 7) + (lane << 2) + e;
}
__device__ __forceinline__ size_t bpermi(int n, int k, int K) {
    int lane = ((n & 7) << 2) + (k & 3);
    int e = (k >> 2) & 3;
    return ((((size_t)(n >> 3)) * (K >> 4) + (k >> 4)) << 7) + (lane << 2) + e;
}
// P A-perm word within a 16-row warp tile (cols = kv)
__device__ __forceinline__ int pword(int m, int c) {
    return ((c >> 3) << 7) + (((m & 7) << 2) + (c & 3)) * 4 + ((m >> 3) & 1) + (((c >> 2) & 1) << 1);
}
__device__ __forceinline__ int vrot(int l) { return ((l & 3) << 3) | (l >> 2); }

// ====== tf32 tensor-core GEMM: CTA 128x128, 4 warps (64x64), 3 stages, 2 CTAs/SM ====
// For GEMM1 (kpos != null), KV-range CTAs also scatter tf32(acc + pos) into g_ap
// (fused conv-A build; bit-identical to the former k_addpos kernel).
__global__ __launch_bounds__(128, 2) void k_tgemm(const float* __restrict__ A,
                                                  const float* __restrict__ B,
                                                  float* __restrict__ C, int N, int K,
                                                  const float* __restrict__ kpos,
                                                  const float* __restrict__ vpos) {
    extern __shared__ float sm[];
    const uint32_t sbase = smem_u32(sm);
    const int tid = threadIdx.x;
    const int wid = tid >> 5, lane = tid & 31;
    const int g = lane >> 2, t = lane & 3;
    const int bm = blockIdx.y * 128, bn = blockIdx.x * 128;
    const int mbw = (wid >> 1) * 4;
    const int nbw = (wid & 1) * 8;
    const int KB8 = K >> 3, KB16 = K >> 4;
    const int NK = K >> 5;

    float acc[4][8][4];
    #pragma unroll
    for (int i = 0; i < 4; i++)
        #pragma unroll
        for (int j = 0; j < 8; j++)
            #pragma unroll
            for (int e = 0; e < 4; e++) acc[i][j][e] = 0.f;

    auto load_stage = [&](int kt, int s) {
        #pragma unroll
        for (int it = 0; it < 16; it++) {
            int seg = tid + it * 128;
            int blk = (seg >> 5) & 31;
            int w16 = seg & 31;
            const float* gp;
            if (seg < 1024) {
                int mbl = blk >> 2, kbl = blk & 3;
                gp = A + ((((size_t)(bm >> 4) + mbl) * KB8 + (kt << 2) + kbl) << 7) + (w16 << 2);
            } else {
                int nbl = blk >> 1, kbl = blk & 1;
                gp = B + ((((size_t)(bn >> 3) + nbl) * KB16 + (kt << 1) + kbl) << 7) + (w16 << 2);
            }
            uint32_t so = sbase + s * 32768 + (seg << 4);
            CP_ASYNC16(so, gp);
        }
        CP_COMMIT();
    };

    load_stage(0, 0);
    load_stage(1, 1);

    for (int kt = 0; kt < NK; kt++) {
        int s = kt - (kt / 3) * 3;
        CP_WAIT1();
        __syncthreads();
        if (kt + 2 < NK) {
            int s2 = (kt + 2) - ((kt + 2) / 3) * 3;
            load_stage(kt + 2, s2);
        } else CP_COMMIT();
        const float* As = sm + s * 8192;
        const float* Bs = As + 4096;
        #pragma unroll
        for (int kp = 0; kp < 2; kp++) {
            uint32_t bfr[8][4];
            #pragma unroll
            for (int j = 0; j < 8; j++)
                *(uint4*)bfr[j] = *(const uint4*)(Bs + (((nbw + j) << 1) + kp) * 128 + (lane << 2));
            #pragma unroll
            for (int h2 = 0; h2 < 2; h2++) {
                int ks = kp * 2 + h2;
                uint32_t afr[4][4];
                #pragma unroll
                for (int i = 0; i < 4; i++)
                    *(uint4*)afr[i] = *(const uint4*)(As + (((mbw + i) << 2) + ks) * 128 + (lane << 2));
                #pragma unroll
                for (int i = 0; i < 4; i++)
                    #pragma unroll
                    for (int j = 0; j < 8; j++) mma_tf32(acc[i][j], afr[i], &bfr[j][2 * h2]);
            }
        }
    }

    #pragma unroll
    for (int i = 0; i < 4; i++)
        #pragma unroll
        for (int j = 0; j < 8; j++) {
            int row = bm + (mbw + i) * 16 + g;
            int col = bn + (nbw + j) * 8 + 2 * t;
            *(float2*)(C + (size_t)row * N + col) = make_float2(acc[i][j][0], acc[i][j][1]);
            *(float2*)(C + (size_t)(row + 8) * N + col) = make_float2(acc[i][j][2], acc[i][j][3]);
        }

    // fused conv-A build (GEMM1, KV N-range only; CTA-uniform branch)
    if (kpos && bn >= KOFF_ && bn < CWOFF_) {
        const float* posb = (bn >= VOFF_) ? vpos : kpos;
        float* apb = g_ap + ((bn >= VOFF_) ? (size_t)32 * 524288 : 0);
        #pragma unroll
        for (int i = 0; i < 4; i++)
            #pragma unroll
            for (int j = 0; j < 8; j++) {
                int row0 = bm + (mbw + i) * 16 + g;
                int col0 = bn + (nbw + j) * 8 + 2 * t;
                #pragma unroll
                for (int e = 0; e < 4; e++) {
                    int row = row0 + ((e >> 1) << 3);
                    int col = col0 + (e & 1);
                    int h = (col >> 6) & 31;
                    int kap = ((row & 63) << 6) + (col & 63);
                    int n = row >> 6;
                    float v = acc[i][j][e] + posb[h * 4096 + kap];
                    apb[(size_t)h * 524288 + apermi(n, kap, 4096)] = to_tf32f(v);
                }
            }
    }
}

// ================= conv as tensor-core GEMM, split-K=4 =====================
__global__ __launch_bounds__(256, 2) void k_tconv() {
    extern __shared__ float sm[];
    const uint32_t sbase = smem_u32(sm);
    const int tid = threadIdx.x;
    const int wid = tid >> 5, lane = tid & 31;
    const int g = lane >> 2, t = lane & 3;
    const int ksp = blockIdx.x;
    const int b = blockIdx.y;
    const float* A = g_ap + (size_t)b * 524288;
    const float* B = g_wtp + (size_t)b * 262144;
    const int mbw = (wid >> 1) * 2;
    const int nbw = (wid & 1) * 4;

    float acc[2][4][4];
    #pragma unroll
    for (int i = 0; i < 2; i++)
        #pragma unroll
        for (int j = 0; j < 4; j++)
            #pragma unroll
            for (int e = 0; e < 4; e++) acc[i][j][e] = 0.f;

    auto load_stage = [&](int kt, int s) {
        #pragma unroll
        for (int it = 0; it < 6; it++) {
            int seg = tid + it * 256;
            const float* gp;
            uint32_t so;
            if (seg < 1024) {
                int blk = seg >> 5, w16 = seg & 31;
                int mbl = blk >> 2, kbl = blk & 3;
                gp = A + (((size_t)mbl * 512 + (kt << 2) + kbl) << 7) + (w16 << 2);
                so = sbase + s * 24576 + (seg << 4);
            } else {
                int sb = seg - 1024;
                int blk = sb >> 5, w16 = sb & 31;
                int nbl = blk >> 1, kbl = blk & 1;
                gp = B + (((size_t)nbl * 256 + (kt << 1) + kbl) << 7) + (w16 << 2);
                so = sbase + s * 24576 + 16384 + (sb << 4);
            }
            CP_ASYNC16(so, gp);
        }
        CP_COMMIT();
    };

    const int kt0 = ksp * 32;
    load_stage(kt0, 0);
    load_stage(kt0 + 1, 1);

    for (int kk = 0; kk < 32; kk++) {
        int s = kk - (kk / 3) * 3;
        CP_WAIT1();
        __syncthreads();
        if (kk + 2 < 32) {
            int s2 = (kk + 2) - ((kk + 2) / 3) * 3;
            load_stage(kt0 + kk + 2, s2);
        } else CP_COMMIT();
        const float* As = sm + s * 6144;
        const float* Bs = As + 4096;
        #pragma unroll
        for (int kp = 0; kp < 2; kp++) {
            uint32_t bfr[4][4];
            #pragma unroll
            for (int j = 0; j < 4; j++)
                *(uint4*)bfr[j] = *(const uint4*)(Bs + (((nbw + j) << 1) + kp) * 128 + (lane << 2));
            #pragma unroll
            for (int h2 = 0; h2 < 2; h2++) {
                int ks4 = kp * 2 + h2;
                uint32_t afr[2][4];
                #pragma unroll
                for (int i = 0; i < 2; i++)
                    *(uint4*)afr[i] = *(const uint4*)(As + (((mbw + i) << 2) + ks4) * 128 + (lane << 2));
                #pragma unroll
                for (int i = 0; i < 2; i++)
                    #pragma unroll
                    for (int j = 0; j < 4; j++) mma_tf32(acc[i][j], afr[i], &bfr[j][2 * h2]);
            }
        }
    }

    int kv = b >> 5, h = b & 31;
    float* out = g_part[kv][ksp] + h * 8192;
    #pragma unroll
    for (int i = 0; i < 2; i++)
        #pragma unroll
        for (int j = 0; j < 4; j++) {
            int row = (mbw + i) * 16 + g;
            int col = (nbw + j) * 8 + 2 * t;
            *(float2*)(out + row * 64 + col) = make_float2(acc[i][j][0], acc[i][j][1]);
            *(float2*)(out + (row + 8) * 64 + col) = make_float2(acc[i][j][2], acc[i][j][3]);
        }
}

// ---------------- conv weights -> B-perm tf32 ----------------
__global__ void k_prepw(const float* __restrict__ kcw, const float* __restrict__ vcw) {
    __shared__ float ts[64 * 65];
    int o = blockIdx.x;
    int b = blockIdx.y;
    int kv = b >> 5, h = b & 31;
    const float* src = (kv ? vcw : kcw) + (size_t)(h * 64 + o) * 4096;
    float* dst = g_wtp + (size_t)b * 262144;
    int tid = threadIdx.x;
    #pragma unroll
    for (int rep = 0; rep < 16; rep++) {
        int i = rep * 4 + (tid >> 6);
        int t = tid & 63;
        ts[t * 65 + i] = src[i * 64 + t];
    }
    __syncthreads();
    #pragma unroll
    for (int rep = 0; rep < 16; rep++) {
        int kappa = rep * 256 + tid;
        int t = kappa >> 6, i = kappa & 63;
        dst[bpermi(o, kappa, 4096)] = to_tf32f(ts[t * 65 + i]);
    }
}

// ---------------- rms norm -> A-perm tf32 ----------------
__global__ void k_rmsnorm(const float* __restrict__ inp, const float* __restrict__ w) {
    int row = blockIdx.x;
    const float* p = inp + (size_t)row * DIM_;
    float ss = 0.f;
    for (int c = threadIdx.x; c < DIM_; c += 256) { float v = p[c]; ss += v * v; }
    #pragma unroll
    for (int o = 16; o > 0; o >>= 1) ss += __shfl_xor_sync(0xffffffffu, ss, o);
    __shared__ float red[8];
    __shared__ float scs;
    if ((threadIdx.x & 31) == 0) red[threadIdx.x >> 5] = ss;
    __syncthreads();
    if (threadIdx.x == 0) {
        float tt = 0.f;
        #pragma unroll
        for (int v = 0; v < 8; v++) tt += red[v];
        scs = rsqrtf(tt * (1.f / (float)DIM_) + RMS_EPS_);
    }
    __syncthreads();
    float sc = scs;
    for (int c = threadIdx.x; c < DIM_; c += 256)
        g_x[apermi(row, c, DIM_)] = to_tf32f(p[c] * sc * w[c]);
}

// ---------------- transpose + concat -> B-perm tf32 ----------------
__global__ void k_prepbt(const float* __restrict__ s0, int c0,
                         const float* __restrict__ s1, int c1,
                         float* __restrict__ o) {
    __shared__ float t[32][33];
    int nt = blockIdx.x * 32, kt = blockIdx.y * 32;
    int tx = threadIdx.x, ty = threadIdx.y;
    #pragma unroll
    for (int r = ty; r < 32; r += 8) {
        int k = kt + r, n = nt + tx;
        float v = 0.f;
        if (n < c0) v = s0[(size_t)k * c0 + n];
        else if (s1 && n < c0 + c1) v = s1[(size_t)k * c1 + (n - c0)];
        t[r][tx] = v;
    }
    __syncthreads();
    #pragma unroll
    for (int r = ty; r < 32; r += 8) {
        int n = nt + r, k = kt + tx;
        o[bpermi(n, k, 2048)] = to_tf32f(t[tx][r]);
    }
}

// ---------------- conv split-K reduce + bias (vectorized) ----------------
__global__ void k_convred(const float* __restrict__ kcb, const float* __restrict__ vcb) {
    int idx = blockIdx.x * 256 + threadIdx.x;
    const int per4 = (H_ * NC_ * DH_) >> 2;
    if (idx >= 2 * per4) return;
    int kv = idx / per4;
    int rem = idx - kv * per4;
    float4 s = *(const float4*)(&g_part[kv][0][rem << 2]);
    #pragma unroll
    for (int ks = 1; ks < KSPLIT_; ks++) {
        float4 p = *(const float4*)(&g_part[kv][ks][rem << 2]);
        s.x += p.x; s.y += p.y; s.z += p.z; s.w += p.w;
    }
    int elem = rem << 2;
    int h = elem >> 13;
    int o = elem & 63;
    float4 bia = *(const float4*)((kv ? vcb : kcb) + h * 64 + o);
    s.x += bia.x; s.y += bia.y; s.z += bia.z; s.w += bia.w;
    *(float4*)(&g_ckv[kv][elem]) = s;
}

// ---- vectorized fills: K (LDG.128 + 4 rotated STS.32), V (4 LDG.32 + STS.128) ----
__device__ __forceinline__ void fill_k(float* Ksm, const float* rowbase, size_t rowstride,
                                       int tid) {
    #pragma unroll
    for (int it = 0; it < 8; it++) {
        int f = tid + it * 256;
        int kv = f >> 4, q = f & 15;
        float4 v4 = *(const float4*)(rowbase + (size_t)kv * rowstride + 4 * q);
        float vals[4] = {v4.x, v4.y, v4.z, v4.w};
        float* dstb = Ksm + ((((kv >> 3) << 2) + (q >> 2)) << 7) + (q & 3);
        int lb = (kv & 7) << 2;
        #pragma unroll
        for (int s = 0; s < 4; s++) {
            int c = (s + (q >> 2)) & 3;
            dstb[(lb + c) << 2] = to_tf32f(vals[c]);
        }
    }
}
__device__ __forceinline__ void fill_v(float* Vsm, const float* rowbase, size_t rowstride,
                                       int tid) {
    #pragma unroll
    for (int it = 0; it < 8; it++) {
        int f = tid + it * 256;
        int d = f & 63, rem = f >> 6;
        int kv16 = rem >> 2, kvlow = rem & 3;
        int kvb = (kv16 << 4) + kvlow;
        const float* s0 = rowbase + (size_t)kvb * rowstride + d;
        float4 o;
        o.x = to_tf32f(s0[0]);
        o.y = to_tf32f(s0[4 * rowstride]);
        o.z = to_tf32f(s0[8 * rowstride]);
        o.w = to_tf32f(s0[12 * rowstride]);
        int lane = (kvlow << 3) + (d & 7);
        *(float4*)(Vsm + ((((d >> 3) << 3) + kv16) << 7) + (lane << 2)) = o;
    }
}

// ===== merged attention: compressed (regs) + local (online) + fused combine =====
__global__ __launch_bounds__(256, 1) void k_attn(const float* __restrict__ bcomb) {
    extern __shared__ float smA[];
    float* Ksm = smA;
    float* Vsm = smA + 8192;
    float* Psm = smA + 16384;
    int a = blockIdx.x, h = blockIdx.y;
    int tid = threadIdx.x, w = tid >> 5, lane = tid & 31;
    int g = lane >> 2, t = lane & 3;
    int r0 = w * 16 + g, r1 = r0 + 8;
    int vr = vrot(lane);
    float* Pw = Psm + w * 2048;

    uint32_t qfr[8][4];
    {
        const float* qb = g_qkv + (size_t)(a * 128 + w * 16) * RS_ + h * 64;
        #pragma unroll
        for (int ks = 0; ks < 8; ks++) {
            qfr[ks][0] = __float_as_uint(to_tf32f(qb[(size_t)g * RS_ + ks * 8 + t]));
            qfr[ks][1] = __float_as_uint(to_tf32f(qb[(size_t)(g + 8) * RS_ + ks * 8 + t]));
            qfr[ks][2] = __float_as_uint(to_tf32f(qb[(size_t)g * RS_ + ks * 8 + t + 4]));
            qfr[ks][3] = __float_as_uint(to_tf32f(qb[(size_t)(g + 8) * RS_ + ks * 8 + t + 4]));
        }
    }

    // ---------------- phase C: compressed branch -> oc (normalized) --------------
    float oc[8][4];
    {
        const int qskip = a >> 4;
        const int kpskip = a >> 3;
        fill_k(Ksm, g_ckv[0] + h * 8192, 64, tid);
        fill_v(Vsm, g_ckv[1] + h * 8192, 64, tid);
        __syncthreads();

        float sacc[16][4];
        #pragma unroll
        for (int jb = 0; jb < 16; jb++)
            #pragma unroll
            for (int e = 0; e < 4; e++) sacc[jb][e] = 0.f;
        #pragma unroll
        for (int qq = 0; qq < 4; qq++) {
            if (qq < qskip) continue;
            #pragma unroll
            for (int kp = 0; kp < 4; kp++) {
                uint32_t bfr[4][4];
                #pragma unroll
                for (int j = 0; j < 4; j++)
                    *(uint4*)bfr[j] = *(const uint4*)(Ksm + ((((qq * 4 + j) << 2) + kp) << 7) + lane * 4);
                #pragma unroll
                for (int h2 = 0; h2 < 2; h2++) {
                    int ks = kp * 2 + h2;
                    #pragma unroll
                    for (int j = 0; j < 4; j++)
                        mma_tf32(sacc[qq * 4 + j], qfr[ks], &bfr[j][2 * h2]);
                }
            }
        }

        int th0 = (a * 128 + r0) >> 6;
        int th1 = (a * 128 + r1) >> 6;
        float mx0 = NEGINF_, mx1 = NEGINF_;
        #pragma unroll
        for (int qq = 0; qq < 4; qq++) {
            if (qq < qskip) continue;
            #pragma unroll
            for (int j = 0; j < 4; j++) {
                int jb = qq * 4 + j;
                int c0 = jb * 8 + 2 * t, c1 = c0 + 1;
                sacc[jb][0] = (c0 >= th0) ? sacc[jb][0] * SCALE_ : NEGINF_;
                sacc[jb][1] = (c1 >= th0) ? sacc[jb][1] * SCALE_ : NEGINF_;
                sacc[jb][2] = (c0 >= th1) ? sacc[jb][2] * SCALE_ : NEGINF_;
                sacc[jb][3] = (c1 >= th1) ? sacc[jb][3] * SCALE_ : NEGINF_;
                mx0 = fmaxf(mx0, fmaxf(sacc[jb][0], sacc[jb][1]));
                mx1 = fmaxf(mx1, fmaxf(sacc[jb][2], sacc[jb][3]));
            }
        }
        mx0 = fmaxf(mx0, __shfl_xor_sync(0xffffffffu, mx0, 1));
        mx0 = fmaxf(mx0, __shfl_xor_sync(0xffffffffu, mx0, 2));
        mx1 = fmaxf(mx1, __shfl_xor_sync(0xffffffffu, mx1, 1));
        mx1 = fmaxf(mx1, __shfl_xor_sync(0xffffffffu, mx1, 2));
        float s0 = 0.f, s1 = 0.f;
        #pragma unroll
        for (int qq = 0; qq < 4; qq++) {
            if (qq < qskip) continue;
            #pragma unroll
            for (int j = 0; j < 4; j++) {
                int jb = qq * 4 + j;
                sacc[jb][0] = __expf(sacc[jb][0] - mx0);
                sacc[jb][1] = __expf(sacc[jb][1] - mx0);
                sacc[jb][2] = __expf(sacc[jb][2] - mx1);
                sacc[jb][3] = __expf(sacc[jb][3] - mx1);
                s0 += sacc[jb][0] + sacc[jb][1];
                s1 += sacc[jb][2] + sacc[jb][3];
                int c0 = jb * 8 + 2 * t;
                Pw[pword(g, c0)]     = to_tf32f(sacc[jb][0]);
                Pw[pword(g, c0 + 1)] = to_tf32f(sacc[jb][1]);
                Pw[pword(g + 8, c0)]     = to_tf32f(sacc[jb][2]);
                Pw[pword(g + 8, c0 + 1)] = to_tf32f(sacc[jb][3]);
            }
        }
        s0 += __shfl_xor_sync(0xffffffffu, s0, 1);
        s0 += __shfl_xor_sync(0xffffffffu, s0, 2);
        s1 += __shfl_xor_sync(0xffffffffu, s1, 1);
        s1 += __shfl_xor_sync(0xffffffffu, s1, 2);
        __syncwarp();

        #pragma unroll
        for (int nb = 0; nb < 8; nb++)
            #pragma unroll
            for (int e = 0; e < 4; e++) oc[nb][e] = 0.f;
        #pragma unroll
        for (int kp = 0; kp < 8; kp++) {
            if (kp < kpskip) continue;
            uint32_t bfr[8][4];
            #pragma unroll
            for (int nb = 0; nb < 8; nb++)
                *(uint4*)bfr[nb] = *(const uint4*)(Vsm + (((nb << 3) + kp) << 7) + vr * 4);
            #pragma unroll
            for (int h2 = 0; h2 < 2; h2++) {
                int ks = kp * 2 + h2;
                uint32_t afr[4];
                *(uint4*)afr = *(const uint4*)(Pw + (ks << 7) + lane * 4);
                #pragma unroll
                for (int nb = 0; nb < 8; nb++)
                    mma_tf32(oc[nb], afr, &bfr[nb][2 * h2]);
            }
        }
        float inv0 = 1.f / s0, inv1 = 1.f / s1;
        #pragma unroll
        for (int nb = 0; nb < 8; nb++) {
            oc[nb][0] *= inv0; oc[nb][1] *= inv0;
            oc[nb][2] *= inv1; oc[nb][3] *= inv1;
        }
    }

    // ---------------- phase L: local branch (online over 2 tiles) ----------------
    float m0 = NEGINF_, m1 = NEGINF_, l0 = 0.f, l1 = 0.f;
    float oacc[8][4];
    #pragma unroll
    for (int nb = 0; nb < 8; nb++)
        #pragma unroll
        for (int e = 0; e < 4; e++) oacc[nb][e] = 0.f;
    int tstart = (a == 0) ? 1 : 0;

    for (int tile = tstart; tile < 2; tile++) {
        __syncthreads();
        int jbase = (a - 1 + tile) * 128;
        {
            const float* kb = g_qkv + (size_t)jbase * RS_ + KOFF_ + h * 64;
            const float* vb = g_qkv + (size_t)jbase * RS_ + VOFF_ + h * 64;
            fill_k(Ksm, kb, RS_, tid);
            fill_v(Vsm, vb, RS_, tid);
        }
        __syncthreads();

        int qlo = (tile == 0) ? (w >> 1) : 0;
        int qhi = (tile == 0) ? 4 : ((w >> 1) + 1);
        int kplo = (tile == 0) ? w : 0;
        int kphi = (tile == 0) ? 8 : (w + 1);

        float sacc[16][4];
        #pragma unroll
        for (int jb = 0; jb < 16; jb++)
            #pragma unroll
            for (int e = 0; e < 4; e++) sacc[jb][e] = 0.f;
        #pragma unroll
        for (int qq = 0; qq < 4; qq++) {
            if (qq < qlo || qq >= qhi) continue;
            #pragma unroll
            for (int kp = 0; kp < 4; kp++) {
                uint32_t bfr[4][4];
                #pragma unroll
                for (int j = 0; j < 4; j++)
                    *(uint4*)bfr[j] = *(const uint4*)(Ksm + ((((qq * 4 + j) << 2) + kp) << 7) + lane * 4);
                #pragma unroll
                for (int h2 = 0; h2 < 2; h2++) {
                    int ks = kp * 2 + h2;
                    #pragma unroll
                    for (int j = 0; j < 4; j++)
                        mma_tf32(sacc[qq * 4 + j], qfr[ks], &bfr[j][2 * h2]);
                }
            }
        }

        float rm0 = NEGINF_, rm1 = NEGINF_;
        #pragma unroll
        for (int qq = 0; qq < 4; qq++) {
            if (qq < qlo || qq >= qhi) continue;
            #pragma unroll
            for (int j = 0; j < 4; j++) {
                int jb = qq * 4 + j;
                int c0 = jb * 8 + 2 * t, c1 = c0 + 1;
                bool a00, a01, a10, a11;
                if (tile == 0) { a00 = c0 >= r0; a01 = c1 >= r0; a10 = c0 >= r1; a11 = c1 >= r1; }
                else           { a00 = c0 <= r0; a01 = c1 <= r0; a10 = c0 <= r1; a11 = c1 <= r1; }
                sacc[jb][0] = a00 ? sacc[jb][0] * SCALE_ : NEGINF_;
                sacc[jb][1] = a01 ? sacc[jb][1] * SCALE_ : NEGINF_;
                sacc[jb][2] = a10 ? sacc[jb][2] * SCALE_ : NEGINF_;
                sacc[jb][3] = a11 ? sacc[jb][3] * SCALE_ : NEGINF_;
                rm0 = fmaxf(rm0, fmaxf(sacc[jb][0], sacc[jb][1]));
                rm1 = fmaxf(rm1, fmaxf(sacc[jb][2], sacc[jb][3]));
            }
        }
        rm0 = fmaxf(rm0, __shfl_xor_sync(0xffffffffu, rm0, 1));
        rm0 = fmaxf(rm0, __shfl_xor_sync(0xffffffffu, rm0, 2));
        rm1 = fmaxf(rm1, __shfl_xor_sync(0xffffffffu, rm1, 1));
        rm1 = fmaxf(rm1, __shfl_xor_sync(0xffffffffu, rm1, 2));
        float mn0 = fmaxf(m0, rm0), mn1 = fmaxf(m1, rm1);
        float corr0 = __expf(m0 - mn0), corr1 = __expf(m1 - mn1);
        float rs0 = 0.f, rs1 = 0.f;
        #pragma unroll
        for (int qq = 0; qq < 4; qq++) {
            if (qq < qlo || qq >= qhi) continue;
            #pragma unroll
            for (int j = 0; j < 4; j++) {
                int jb = qq * 4 + j;
                sacc[jb][0] = __expf(sacc[jb][0] - mn0);
                sacc[jb][1] = __expf(sacc[jb][1] - mn0);
                sacc[jb][2] = __expf(sacc[jb][2] - mn1);
                sacc[jb][3] = __expf(sacc[jb][3] - mn1);
                rs0 += sacc[jb][0] + sacc[jb][1];
                rs1 += sacc[jb][2] + sacc[jb][3];
                int c0 = jb * 8 + 2 * t;
                Pw[pword(g, c0)]     = to_tf32f(sacc[jb][0]);
                Pw[pword(g, c0 + 1)] = to_tf32f(sacc[jb][1]);
                Pw[pword(g + 8, c0)]     = to_tf32f(sacc[jb][2]);
                Pw[pword(g + 8, c0 + 1)] = to_tf32f(sacc[jb][3]);
            }
        }
        rs0 += __shfl_xor_sync(0xffffffffu, rs0, 1);
        rs0 += __shfl_xor_sync(0xffffffffu, rs0, 2);
        rs1 += __shfl_xor_sync(0xffffffffu, rs1, 1);
        rs1 += __shfl_xor_sync(0xffffffffu, rs1, 2);
        l0 = l0 * corr0 + rs0;
        l1 = l1 * corr1 + rs1;
        #pragma unroll
        for (int nb = 0; nb < 8; nb++) {
            oacc[nb][0] *= corr0; oacc[nb][1] *= corr0;
            oacc[nb][2] *= corr1; oacc[nb][3] *= corr1;
        }
        m0 = mn0; m1 = mn1;
        __syncwarp();

        #pragma unroll
        for (int kp = 0; kp < 8; kp++) {
            if (kp < kplo || kp >= kphi) continue;
            uint32_t bfr[8][4];
            #pragma unroll
            for (int nb = 0; nb < 8; nb++)
                *(uint4*)bfr[nb] = *(const uint4*)(Vsm + (((nb << 3) + kp) << 7) + vr * 4);
            #pragma unroll
            for (int h2 = 0; h2 < 2; h2++) {
                int ks = kp * 2 + h2;
                uint32_t afr[4];
                *(uint4*)afr = *(const uint4*)(Pw + (ks << 7) + lane * 4);
                #pragma unroll
                for (int nb = 0; nb < 8; nb++)
                    mma_tf32(oacc[nb], afr, &bfr[nb][2 * h2]);
            }
        }
    }

    // ---------------- fused combine epilogue ----------------
    float inv0 = 1.f / l0, inv1 = 1.f / l1;
    size_t i0 = a * 128 + r0, i1 = i0 + 8;
    float wl0, c2_0, wl1, c2_1;
    {
        const float* lg = g_qkv + i0 * RS_ + CWOFF_ + h * 3;
        float z0 = lg[0] + bcomb[h * 3 + 0];
        float z1 = lg[1] + bcomb[h * 3 + 1];
        float z2 = lg[2] + bcomb[h * 3 + 2];
        wl0 = 1.f / (1.f + __expf(-z0)) + 1.f / (1.f + __expf(-z1));
        c2_0 = 1.f / (1.f + __expf(-z2));
    }
    {
        const float* lg = g_qkv + i1 * RS_ + CWOFF_ + h * 3;
        float z0 = lg[0] + bcomb[h * 3 + 0];
        float z1 = lg[1] + bcomb[h * 3 + 1];
        float z2 = lg[2] + bcomb[h * 3 + 2];
        wl1 = 1.f / (1.f + __expf(-z0)) + 1.f / (1.f + __expf(-z1));
        c2_1 = 1.f / (1.f + __expf(-z2));
    }
    int cbase = h * 64;
    #pragma unroll
    for (int nb = 0; nb < 8; nb++) {
        int d0 = nb * 8 + 2 * t;
        g_y[apermi((int)i0, cbase + d0,     DIM_)] = to_tf32f(wl0 * (oacc[nb][0] * inv0) + c2_0 * oc[nb][0]);
        g_y[apermi((int)i0, cbase + d0 + 1, DIM_)] = to_tf32f(wl0 * (oacc[nb][1] * inv0) + c2_0 * oc[nb][1]);
        g_y[apermi((int)i1, cbase + d0,     DIM_)] = to_tf32f(wl1 * (oacc[nb][2] * inv1) + c2_1 * oc[nb][2]);
        g_y[apermi((int)i1, cbase + d0 + 1, DIM_)] = to_tf32f(wl1 * (oacc[nb][3] * inv1) + c2_1 * oc[nb][3]);
    }
}

// ---------------- launch ----------------
extern "C" void kernel_launch(void* const* d_in, const int* in_sizes, int n_in,
                              void* d_out, int out_size) {
    const float* inp    = (const float*)d_in[0];
    const float* rms_w  = (const float*)d_in[1];
    const float* w_qkv  = (const float*)d_in[2];
    const float* k_pos  = (const float*)d_in[3];
    const float* v_pos  = (const float*)d_in[4];
    const float* kc_w   = (const float*)d_in[5];
    const float* kc_b   = (const float*)d_in[6];
    const float* vc_w   = (const float*)d_in[7];
    const float* vc_b   = (const float*)d_in[8];
    // d_in[9] = mem_kv: provably unused (always masked)
    const float* w_comb = (const float*)d_in[10];
    const float* b_comb = (const float*)d_in[11];
    const float* w_out  = (const float*)d_in[12];
    float* out = (float*)d_out;

    const int GSMEM = 3 * 32768;   // 98304 (3-stage, proven)
    const int CSMEM = 3 * 24576;   // 73728
    const int ASMEM = 131072;
    cudaFuncSetAttribute(k_tgemm, cudaFuncAttributeMaxDynamicSharedMemorySize, GSMEM);
    cudaFuncSetAttribute(k_tconv, cudaFuncAttributeMaxDynamicSharedMemorySize, CSMEM);
    cudaFuncSetAttribute(k_attn, cudaFuncAttributeMaxDynamicSharedMemorySize, ASMEM);

    float *px, *pwb1, *pwb2, *pqkv, *py;
    cudaGetSymbolAddress((void**)&px, g_x);
    cudaGetSymbolAddress((void**)&pwb1, g_wb1);
    cudaGetSymbolAddress((void**)&pwb2, g_wb2);
    cudaGetSymbolAddress((void**)&pqkv, g_qkv);
    cudaGetSymbolAddress((void**)&py, g_y);

    dim3 tb(32, 8);
    k_rmsnorm<<<S_, 256>>>(inp, rms_w);
    k_prepbt<<<dim3(RS_ / 32, DIM_ / 32), tb>>>(w_qkv, 6144, w_comb, 96, pwb1);
    k_prepbt<<<dim3(DIM_ / 32, DIM_ / 32), tb>>>(w_out, 2048, (const float*)0, 0, pwb2);
    k_prepw<<<dim3(64, 64), 256>>>(kc_w, vc_w);
    k_tgemm<<<dim3(RS_ / 128, S_ / 128), 128, GSMEM>>>(px, pwb1, pqkv, RS_, DIM_, k_pos, v_pos);
    k_tconv<<<dim3(KSPLIT_, 64), 256, CSMEM>>>();
    k_convred<<<512, 256>>>(kc_b, vc_b);
    k_attn<<<dim3(64, 32), 256, ASMEM>>>(b_comb);
    k_tgemm<<<dim3(DIM_ / 128, S_ / 128), 128, GSMEM>>>(py, pwb2, out, DIM_, DIM_,
                                                        (const float*)0, (const float*)0);
}